// round 4
// baseline (speedup 1.0000x reference)
#include <cuda_runtime.h>
#include <cstdint>
#include <cstddef>

#define BB 2
#define SS 2048
#define HID 512
#define NH 8
#define DH 64
#define BSROWS (BB*SS)   // 4096

// Scratch (device globals — allocation-free rule)
__device__ __align__(16) float g_q[BSROWS*HID];
__device__ __align__(16) float g_k[BSROWS*HID];
__device__ __align__(16) float g_v[BSROWS*HID];
__device__ __align__(16) float g_x[BSROWS*HID];
__device__ __align__(16) float g_cr[BSROWS*NH*4];
__device__ __align__(16) float g_rinv[BB*NH*SS];

// ---------------------------------------------------------------------------
// GEMM: C[M=4096, N=512] = A[4096, 512] @ W[512, 512] + bias
// 64x64 tile, 256 threads, 4x4 per thread, K-tile 16, fp32.
// ---------------------------------------------------------------------------
__global__ __launch_bounds__(256) void gemm_bias_kernel(
    const float* __restrict__ A, const float* __restrict__ W,
    const float* __restrict__ bias, float* __restrict__ C)
{
    __shared__ float At[16*65];   // A transposed: At[k][i]  (scalar access only)
    __shared__ float Ws[16*64];   // W natural:    Ws[k][n]  (stride 64 -> aligned f4)
    const int tid = threadIdx.x;
    const int tx = tid & 15, ty = tid >> 4;
    const int row0 = blockIdx.y * 64, col0 = blockIdx.x * 64;

    float acc[4][4] = {};

    for (int k0 = 0; k0 < HID; k0 += 16) {
        {   // load A tile 64x16 (transposed into smem)
            int i = tid >> 2, kq = (tid & 3) << 2;
            float4 a = *(const float4*)(A + (size_t)(row0 + i)*HID + k0 + kq);
            At[(kq+0)*65 + i] = a.x;
            At[(kq+1)*65 + i] = a.y;
            At[(kq+2)*65 + i] = a.z;
            At[(kq+3)*65 + i] = a.w;
        }
        {   // load W tile 16x64
            int kk = tid >> 4, n = (tid & 15) << 2;
            *(float4*)(Ws + kk*64 + n) =
                *(const float4*)(W + (size_t)(k0 + kk)*HID + col0 + n);
        }
        __syncthreads();
#pragma unroll
        for (int kk = 0; kk < 16; ++kk) {
            float a[4];
#pragma unroll
            for (int r = 0; r < 4; ++r) a[r] = At[kk*65 + ty*4 + r];
            float4 bb = *(float4*)(Ws + kk*64 + tx*4);   // stride 64: 16B-aligned
            float bvv[4] = {bb.x, bb.y, bb.z, bb.w};
#pragma unroll
            for (int r = 0; r < 4; ++r)
#pragma unroll
                for (int c = 0; c < 4; ++c)
                    acc[r][c] += a[r] * bvv[c];
        }
        __syncthreads();
    }

    float4 bv = *(const float4*)(bias + col0 + tx*4);
#pragma unroll
    for (int r = 0; r < 4; ++r) {
        float4 o = make_float4(acc[r][0] + bv.x, acc[r][1] + bv.y,
                               acc[r][2] + bv.z, acc[r][3] + bv.w);
        *(float4*)(C + (size_t)(row0 + ty*4 + r)*HID + col0 + tx*4) = o;
    }
}

// ---------------------------------------------------------------------------
// cr[b,i,h,r] = sum_d (q+k)[b,i,h,d] * rel_table[r,d]   (r = 0..2)
// One warp per (b,i,h); lane handles 2 d's.
// ---------------------------------------------------------------------------
__global__ void cr_kernel(const float* __restrict__ q, const float* __restrict__ k,
                          const float* __restrict__ rel, float* __restrict__ cr)
{
    int gw = (int)((blockIdx.x * blockDim.x + threadIdx.x) >> 5);
    int lane = threadIdx.x & 31;
    if (gw >= BSROWS*NH) return;
    int row = gw >> 3, h = gw & 7;
    const float* qp = q + (size_t)row*HID + h*DH;
    const float* kp = k + (size_t)row*HID + h*DH;
    float2 qv = *(const float2*)(qp + lane*2);
    float2 kv = *(const float2*)(kp + lane*2);
    float a0 = qv.x + kv.x, a1 = qv.y + kv.y;
#pragma unroll
    for (int r = 0; r < 3; ++r) {
        float2 rv = *(const float2*)(rel + r*DH + lane*2);
        float s = a0*rv.x + a1*rv.y;
        s += __shfl_xor_sync(0xffffffffu, s, 16);
        s += __shfl_xor_sync(0xffffffffu, s, 8);
        s += __shfl_xor_sync(0xffffffffu, s, 4);
        s += __shfl_xor_sync(0xffffffffu, s, 2);
        s += __shfl_xor_sync(0xffffffffu, s, 1);
        if (lane == 0) cr[(size_t)gw*4 + r] = s;
    }
    if (lane == 0) cr[(size_t)gw*4 + 3] = 0.f;
}

// ---------------------------------------------------------------------------
// Fused attention: per (b,h, 64-row i-tile):
//   S = Q Kt + cr[p]  -> p = exp(S/8) (unnormalized; scores bounded;
//   softmax is shift-invariant so this matches the reference)
//   write p to attn buffer, accumulate rowsum and O = P V, scale O by 1/rowsum.
// Dynamic smem: Qt(64x65) | Kt/Pt union(64x65) | Vs(64x64) | crs(64x4)
// NOTE: KtPt stride is 65 (odd) -> ALL KtPt accesses must be scalar LDS.
// ---------------------------------------------------------------------------
__global__ __launch_bounds__(256) void attn_kernel(
    const float* __restrict__ q, const float* __restrict__ k,
    const float* __restrict__ v, const float* __restrict__ cr,
    const int* __restrict__ pos, const unsigned char* __restrict__ mask,
    float* __restrict__ attn, float* __restrict__ x, float* __restrict__ rinv)
{
    extern __shared__ float sm[];
    float* Qt   = sm;            // 64*65 = 4160
    float* KtPt = sm + 4160;     // 64*65
    float* Vs   = sm + 8320;     // 64*64 = 4096
    float* crs  = sm + 12416;    // 64*4  = 256   (total 12672 floats = 50688 B)

    const int tid = threadIdx.x;
    const int tx = tid & 15, ty = tid >> 4;
    const int bh = blockIdx.y, b = bh >> 3, h = bh & 7;
    const int i0 = blockIdx.x * 64;
    const int iy = ty * 4;

    // load Q tile transposed (Qt[d][i]); resident for entire block
#pragma unroll
    for (int pass = 0; pass < 4; ++pass) {
        int idx = pass*256 + tid;
        int i = idx >> 4, d = (idx & 15) << 2;
        float4 qv = *(const float4*)(q + (size_t)(b*SS + i0 + i)*HID + h*DH + d);
        Qt[(d+0)*65 + i] = qv.x;
        Qt[(d+1)*65 + i] = qv.y;
        Qt[(d+2)*65 + i] = qv.z;
        Qt[(d+3)*65 + i] = qv.w;
    }
    {   // load cr for the 64 i-rows (stride-4 layout)
        int i = tid >> 2, r = tid & 3;
        crs[i*4 + r] = cr[(size_t)((b*SS + i0 + i)*NH + h)*4 + r];
    }

    float o[4][4] = {};
    float rsum[4] = {};

    for (int j0 = 0; j0 < SS; j0 += 64) {
        __syncthreads();   // previous iter's Pt/Vs reads finished (also covers Qt/crs stores)
#pragma unroll
        for (int pass = 0; pass < 4; ++pass) {
            int idx = pass*256 + tid;
            int j = idx >> 4, d = (idx & 15) << 2;
            size_t goff = (size_t)(b*SS + j0 + j)*HID + h*DH + d;
            float4 kv = *(const float4*)(k + goff);
            KtPt[(d+0)*65 + j] = kv.x;
            KtPt[(d+1)*65 + j] = kv.y;
            KtPt[(d+2)*65 + j] = kv.z;
            KtPt[(d+3)*65 + j] = kv.w;
            *(float4*)(Vs + j*64 + d) = *(const float4*)(v + goff);
        }
        __syncthreads();   // tiles ready

        // ---- S tile: 64x64, contraction over d ----
        float acc[4][4] = {};
#pragma unroll
        for (int kk = 0; kk < 64; ++kk) {
            float a[4];
#pragma unroll
            for (int r = 0; r < 4; ++r) a[r] = Qt[kk*65 + iy + r];
            float bvv[4];        // SCALAR loads: stride 65 is not 16B-aligned
#pragma unroll
            for (int c = 0; c < 4; ++c) bvv[c] = KtPt[kk*65 + tx*4 + c];
#pragma unroll
            for (int r = 0; r < 4; ++r)
#pragma unroll
                for (int c = 0; c < 4; ++c)
                    acc[r][c] += a[r] * bvv[c];
        }

        // ---- rel-bias gather + mask + exp + attn write + rowsum ----
        const int jc = j0 + tx*4;
#pragma unroll
        for (int r = 0; r < 4; ++r) {
            int gi = i0 + iy + r;
            int4 pp = *(const int4*)(pos + (size_t)gi*SS + jc);
            uchar4 mm = *(const uchar4*)(mask + (size_t)b*SS*SS + (size_t)gi*SS + jc);
            const float* cp = crs + (iy + r)*4;
            float s0 = (acc[r][0] + cp[pp.x]) * 0.125f;
            float s1 = (acc[r][1] + cp[pp.y]) * 0.125f;
            float s2 = (acc[r][2] + cp[pp.z]) * 0.125f;
            float s3 = (acc[r][3] + cp[pp.w]) * 0.125f;
            float p0 = mm.x ? 0.f : expf(s0);
            float p1 = mm.y ? 0.f : expf(s1);
            float p2 = mm.z ? 0.f : expf(s2);
            float p3 = mm.w ? 0.f : expf(s3);
            rsum[r] += (p0 + p1) + (p2 + p3);
            *(float4*)(attn + ((size_t)bh*SS + gi)*SS + jc) =
                make_float4(p0, p1, p2, p3);
            acc[r][0] = p0; acc[r][1] = p1; acc[r][2] = p2; acc[r][3] = p3;
        }

        __syncthreads();   // all Kt reads done -> safe to overwrite with Pt
#pragma unroll
        for (int r = 0; r < 4; ++r)
#pragma unroll
            for (int c = 0; c < 4; ++c)
                KtPt[(tx*4 + c)*65 + iy + r] = acc[r][c];   // Pt[j][i], scalar
        __syncthreads();   // Pt ready

        // ---- O += P V, contraction over j ----
#pragma unroll
        for (int kk = 0; kk < 64; ++kk) {
            float p[4];
#pragma unroll
            for (int r = 0; r < 4; ++r) p[r] = KtPt[kk*65 + iy + r];  // scalar
            float4 vv = *(float4*)(Vs + kk*64 + tx*4);   // stride 64: aligned
            float vvv[4] = {vv.x, vv.y, vv.z, vv.w};
#pragma unroll
            for (int r = 0; r < 4; ++r)
#pragma unroll
                for (int c = 0; c < 4; ++c)
                    o[r][c] += p[r] * vvv[c];
        }
    }

    // reduce rowsums across the 16 tx lanes (contiguous within half-warp)
#pragma unroll
    for (int r = 0; r < 4; ++r) {
        float s = rsum[r];
        s += __shfl_xor_sync(0xffffffffu, s, 8, 16);
        s += __shfl_xor_sync(0xffffffffu, s, 4, 16);
        s += __shfl_xor_sync(0xffffffffu, s, 2, 16);
        s += __shfl_xor_sync(0xffffffffu, s, 1, 16);
        rsum[r] = 1.0f / s;
    }
    if (tx == 0) {
#pragma unroll
        for (int r = 0; r < 4; ++r)
            rinv[(size_t)bh*SS + i0 + iy + r] = rsum[r];
    }
#pragma unroll
    for (int r = 0; r < 4; ++r) {
        float4 ov = make_float4(o[r][0]*rsum[r], o[r][1]*rsum[r],
                                o[r][2]*rsum[r], o[r][3]*rsum[r]);
        *(float4*)(x + (size_t)(b*SS + i0 + iy + r)*HID + h*DH + tx*4) = ov;
    }
}

// ---------------------------------------------------------------------------
// Normalize attn rows by the precomputed inverse row sums (streaming).
// ---------------------------------------------------------------------------
__global__ void norm_kernel(float* __restrict__ attn, const float* __restrict__ rinv)
{
    const size_t n4 = (size_t)BB*NH*SS*SS/4;   // 16,777,216 float4s
    for (size_t idx = (size_t)blockIdx.x*blockDim.x + threadIdx.x; idx < n4;
         idx += (size_t)gridDim.x*blockDim.x) {
        float inv = rinv[idx >> 9];            // 512 float4 per attn row
        float4 v = ((const float4*)attn)[idx];
        v.x *= inv; v.y *= inv; v.z *= inv; v.w *= inv;
        ((float4*)attn)[idx] = v;
    }
}

// ---------------------------------------------------------------------------
extern "C" void kernel_launch(void* const* d_in, const int* in_sizes, int n_in,
                              void* d_out, int out_size)
{
    const float* query = (const float*)d_in[0];
    const float* key_  = (const float*)d_in[1];
    const float* value = (const float*)d_in[2];
    const unsigned char* mask = (const unsigned char*)d_in[3];
    const int*   pos   = (const int*)d_in[4];
    const float* Wq = (const float*)d_in[5];
    const float* bq = (const float*)d_in[6];
    const float* Wk = (const float*)d_in[7];
    const float* bk = (const float*)d_in[8];
    const float* Wv = (const float*)d_in[9];
    const float* bv = (const float*)d_in[10];
    const float* Wo = (const float*)d_in[11];
    const float* bo = (const float*)d_in[12];
    const float* rel = (const float*)d_in[13];

    float* out  = (float*)d_out;                     // (B,S,HID)
    float* attn = out + (size_t)BSROWS*HID;          // (B,H,S,S)

    float *qb, *kb, *vb, *xb, *crb, *rb;
    cudaGetSymbolAddress((void**)&qb, g_q);
    cudaGetSymbolAddress((void**)&kb, g_k);
    cudaGetSymbolAddress((void**)&vb, g_v);
    cudaGetSymbolAddress((void**)&xb, g_x);
    cudaGetSymbolAddress((void**)&crb, g_cr);
    cudaGetSymbolAddress((void**)&rb, g_rinv);

    const int attn_smem = 12672 * 4;   // 50688 B > 48K static limit
    cudaFuncSetAttribute(attn_kernel,
                         cudaFuncAttributeMaxDynamicSharedMemorySize, attn_smem);

    dim3 gemm_grid(HID/64, BSROWS/64);   // (8, 64)
    gemm_bias_kernel<<<gemm_grid, 256>>>(query, Wq, bq, qb);
    gemm_bias_kernel<<<gemm_grid, 256>>>(key_,  Wk, bk, kb);
    gemm_bias_kernel<<<gemm_grid, 256>>>(value, Wv, bv, vb);

    cr_kernel<<<(BSROWS*NH*32 + 255)/256, 256>>>(qb, kb, rel, crb);

    attn_kernel<<<dim3(SS/64, BB*NH), 256, attn_smem>>>(
        qb, kb, vb, crb, pos, mask, attn, xb, rb);

    norm_kernel<<<2048, 256>>>(attn, rb);

    gemm_bias_kernel<<<gemm_grid, 256>>>(xb, Wo, bo, out);
}

// round 6
// speedup vs baseline: 1.1062x; 1.1062x over previous
#include <cuda_runtime.h>
#include <cuda_bf16.h>
#include <cstdint>
#include <cstddef>

#define BB 2
#define SS 2048
#define HID 512
#define NH 8
#define DH 64
#define BSROWS (BB*SS)   // 4096

// tcgen05 is an arch-SPECIFIC feature: it must only be emitted in the
// sm_103a/sm_100a compilation passes, never in the generic compute_103 pass
// (ptxas rejects it there — that was the Round-5 failure).
#if defined(__CUDA_ARCH_FEAT_SM103_ALL) || defined(__CUDA_ARCH_FEAT_SM100_ALL) || \
    (defined(__CUDA_ARCH_SPECIFIC__) && (__CUDA_ARCH_SPECIFIC__ >= 1000))
#define TCG_OK 1
#else
#define TCG_OK 0
#endif

// Scratch (device globals — allocation-free rule)
__device__ __align__(16) float g_q[BSROWS*HID];
__device__ __align__(16) float g_k[BSROWS*HID];
__device__ __align__(16) float g_v[BSROWS*HID];
__device__ __align__(16) float g_x[BSROWS*HID];
__device__ __align__(16) float g_cr[BSROWS*NH*4];
__device__ __align__(16) float g_rinv[BB*NH*SS];

// ===========================================================================
// GEMM: C[4096,512] = A @ W + bias (fp32 SIMT)
// ===========================================================================
__global__ __launch_bounds__(256) void gemm_bias_kernel(
    const float* __restrict__ A, const float* __restrict__ W,
    const float* __restrict__ bias, float* __restrict__ C)
{
    __shared__ float At[16*65];
    __shared__ float Ws[16*64];
    const int tid = threadIdx.x;
    const int tx = tid & 15, ty = tid >> 4;
    const int row0 = blockIdx.y * 64, col0 = blockIdx.x * 64;
    float acc[4][4] = {};
    for (int k0 = 0; k0 < HID; k0 += 16) {
        {
            int i = tid >> 2, kq = (tid & 3) << 2;
            float4 a = *(const float4*)(A + (size_t)(row0 + i)*HID + k0 + kq);
            At[(kq+0)*65 + i] = a.x; At[(kq+1)*65 + i] = a.y;
            At[(kq+2)*65 + i] = a.z; At[(kq+3)*65 + i] = a.w;
        }
        {
            int kk = tid >> 4, n = (tid & 15) << 2;
            *(float4*)(Ws + kk*64 + n) = *(const float4*)(W + (size_t)(k0 + kk)*HID + col0 + n);
        }
        __syncthreads();
#pragma unroll
        for (int kk = 0; kk < 16; ++kk) {
            float a[4];
#pragma unroll
            for (int r = 0; r < 4; ++r) a[r] = At[kk*65 + ty*4 + r];
            float4 bb = *(float4*)(Ws + kk*64 + tx*4);
            float bvv[4] = {bb.x, bb.y, bb.z, bb.w};
#pragma unroll
            for (int r = 0; r < 4; ++r)
#pragma unroll
                for (int c = 0; c < 4; ++c) acc[r][c] += a[r] * bvv[c];
        }
        __syncthreads();
    }
    float4 bv = *(const float4*)(bias + col0 + tx*4);
#pragma unroll
    for (int r = 0; r < 4; ++r) {
        float4 o = make_float4(acc[r][0]+bv.x, acc[r][1]+bv.y, acc[r][2]+bv.z, acc[r][3]+bv.w);
        *(float4*)(C + (size_t)(row0 + ty*4 + r)*HID + col0 + tx*4) = o;
    }
}

// ===========================================================================
// cr_kernel
// ===========================================================================
__global__ void cr_kernel(const float* __restrict__ q, const float* __restrict__ k,
                          const float* __restrict__ rel, float* __restrict__ cr)
{
    int gw = (int)((blockIdx.x * blockDim.x + threadIdx.x) >> 5);
    int lane = threadIdx.x & 31;
    if (gw >= BSROWS*NH) return;
    int row = gw >> 3, h = gw & 7;
    const float* qp = q + (size_t)row*HID + h*DH;
    const float* kp = k + (size_t)row*HID + h*DH;
    float2 qv = *(const float2*)(qp + lane*2);
    float2 kv = *(const float2*)(kp + lane*2);
    float a0 = qv.x + kv.x, a1 = qv.y + kv.y;
#pragma unroll
    for (int r = 0; r < 3; ++r) {
        float2 rv = *(const float2*)(rel + r*DH + lane*2);
        float s = a0*rv.x + a1*rv.y;
        s += __shfl_xor_sync(0xffffffffu, s, 16);
        s += __shfl_xor_sync(0xffffffffu, s, 8);
        s += __shfl_xor_sync(0xffffffffu, s, 4);
        s += __shfl_xor_sync(0xffffffffu, s, 2);
        s += __shfl_xor_sync(0xffffffffu, s, 1);
        if (lane == 0) cr[(size_t)gw*4 + r] = s;
    }
    if (lane == 0) cr[(size_t)gw*4 + 3] = 0.f;
}

// ===========================================================================
// tcgen05 attention (only in arch-specific passes)
// ===========================================================================
#define SM_TPTR   0
#define SM_SBAR   8
#define SM_PVBAR  16
#define SM_QH     1024
#define SM_QL     17408
#define SM_KH     33792
#define SM_KL     41984
#define SM_VTH    50176
#define SM_VTL    58368
#define SM_TOTAL  66560

#define TM_S   0
#define TM_O   64
#define TM_PH  128
#define TM_PL  160
#define TM_COLS 256

#if TCG_OK
__device__ __forceinline__ uint32_t elect_one_pred() {
    uint32_t pred;
    asm volatile("{\n\t.reg .pred p;\n\telect.sync _|p, 0xFFFFFFFF;\n\t"
                 "selp.b32 %0, 1, 0, p;\n\t}" : "=r"(pred));
    return pred;
}
__device__ __forceinline__ uint32_t smem_u32(const void* p) {
    uint32_t a;
    asm("{ .reg .u64 t; cvta.to.shared.u64 t, %1; cvt.u32.u64 %0, t; }"
        : "=r"(a) : "l"(p));
    return a;
}
#define TCG_ALLOC(sa, n)   asm volatile("tcgen05.alloc.cta_group::1.sync.aligned.shared::cta.b32 [%0], %1;" :: "r"((uint32_t)(sa)), "r"((uint32_t)(n)) : "memory")
#define TCG_DEALLOC(t, n)  asm volatile("tcgen05.dealloc.cta_group::1.sync.aligned.b32 %0, %1;" :: "r"(t), "r"((uint32_t)(n)))
#define TCG_WAIT_LD()      asm volatile("tcgen05.wait::ld.sync.aligned;" ::: "memory")
#define TCG_WAIT_ST()      asm volatile("tcgen05.wait::st.sync.aligned;" ::: "memory")
#define TCG_FENCE_BEFORE() asm volatile("tcgen05.fence::before_thread_sync;" ::: "memory")
#define TCG_FENCE_AFTER()  asm volatile("tcgen05.fence::after_thread_sync;" ::: "memory")
#define TCG_COMMIT(mb)     asm volatile("tcgen05.commit.cta_group::1.mbarrier::arrive::one.shared::cluster.b64 [%0];" :: "r"((uint32_t)(mb)) : "memory")
#define FENCE_ASYNC()      asm volatile("fence.proxy.async.shared::cta;" ::: "memory")
#define MBAR_INIT(mb, c)   asm volatile("mbarrier.init.shared.b64 [%0], %1;" :: "r"((uint32_t)(mb)), "r"((uint32_t)(c)) : "memory")
#define MBAR_INVAL(mb)     asm volatile("mbarrier.inval.shared.b64 [%0];" :: "r"((uint32_t)(mb)) : "memory")

#define MBAR_WAIT(mb, ph) do { \
    uint32_t _m = (uint32_t)(mb), _p = (uint32_t)(ph), _d; \
    asm volatile("{\n\t.reg .pred p;\n\t" \
        "mbarrier.try_wait.parity.acquire.cta.shared::cta.b64 p, [%1], %2;\n\t" \
        "selp.b32 %0, 1, 0, p;\n\t}" : "=r"(_d) : "r"(_m), "r"(_p) : "memory"); \
    if (!_d) { \
        asm volatile("{\n\t.reg .pred P1;\n\t" \
            "WL_%=:\n\t" \
            "mbarrier.try_wait.parity.acquire.cta.shared::cta.b64 P1, [%0], %1, 0x989680;\n\t" \
            "@P1 bra.uni WD_%=;\n\t" \
            "bra.uni WL_%=;\n\t" \
            "WD_%=:\n\t}" :: "r"(_m), "r"(_p) : "memory"); \
    } \
} while (0)

#define TCG_LD_X32(r, ta) \
    asm volatile("tcgen05.ld.sync.aligned.32x32b.x32.b32 " \
        "{%0, %1, %2, %3, %4, %5, %6, %7, %8, %9, %10, %11, %12, %13, %14, %15, " \
        " %16, %17, %18, %19, %20, %21, %22, %23, %24, %25, %26, %27, %28, %29, %30, %31}, [%32];" \
        : "=r"((r)[0]),  "=r"((r)[1]),  "=r"((r)[2]),  "=r"((r)[3]), \
          "=r"((r)[4]),  "=r"((r)[5]),  "=r"((r)[6]),  "=r"((r)[7]), \
          "=r"((r)[8]),  "=r"((r)[9]),  "=r"((r)[10]), "=r"((r)[11]), \
          "=r"((r)[12]), "=r"((r)[13]), "=r"((r)[14]), "=r"((r)[15]), \
          "=r"((r)[16]), "=r"((r)[17]), "=r"((r)[18]), "=r"((r)[19]), \
          "=r"((r)[20]), "=r"((r)[21]), "=r"((r)[22]), "=r"((r)[23]), \
          "=r"((r)[24]), "=r"((r)[25]), "=r"((r)[26]), "=r"((r)[27]), \
          "=r"((r)[28]), "=r"((r)[29]), "=r"((r)[30]), "=r"((r)[31]) \
        : "r"(ta))

#define TCG_ST_X16(ta, r) \
    asm volatile("tcgen05.st.sync.aligned.32x32b.x16.b32 [%0], " \
        "{%1, %2, %3, %4, %5, %6, %7, %8, %9, %10, %11, %12, %13, %14, %15, %16};" \
        :: "r"(ta), \
           "r"((r)[0]),  "r"((r)[1]),  "r"((r)[2]),  "r"((r)[3]), \
           "r"((r)[4]),  "r"((r)[5]),  "r"((r)[6]),  "r"((r)[7]), \
           "r"((r)[8]),  "r"((r)[9]),  "r"((r)[10]), "r"((r)[11]), \
           "r"((r)[12]), "r"((r)[13]), "r"((r)[14]), "r"((r)[15]) \
        : "memory")

__device__ __forceinline__ void mma_f16_ss(uint32_t d_tmem, uint64_t a_desc,
                                           uint64_t b_desc, uint32_t idesc, bool acc) {
    uint32_t en = acc ? 1u : 0u;
    asm volatile("{\n\t.reg .pred p;\n\tsetp.ne.u32 p, %5, 0;\n\t"
        "tcgen05.mma.cta_group::1.kind::f16 [%0], %1, %2, %3, {%4, %4, %4, %4}, p;\n\t}"
        :: "r"(d_tmem), "l"(a_desc), "l"(b_desc), "r"(idesc), "r"(0u), "r"(en) : "memory");
}
__device__ __forceinline__ void mma_f16_ts(uint32_t d_tmem, uint32_t a_tmem,
                                           uint64_t b_desc, uint32_t idesc, bool acc) {
    uint32_t en = acc ? 1u : 0u;
    asm volatile("{\n\t.reg .pred p;\n\tsetp.ne.u32 p, %5, 0;\n\t"
        "tcgen05.mma.cta_group::1.kind::f16 [%0], [%1], %2, %3, {%4, %4, %4, %4}, p;\n\t}"
        :: "r"(d_tmem), "r"(a_tmem), "l"(b_desc), "r"(idesc), "r"(0u), "r"(en) : "memory");
}

static constexpr uint64_t SMEM_DESC_BASE_SW128 =
    (uint64_t(2) << 61) | (uint64_t(1) << 46) | (uint64_t(64) << 32) | (uint64_t(1) << 16);
#define MK_DESC(a) (SMEM_DESC_BASE_SW128 | ((uint64_t)((a) >> 4) & 0x3FFF))
#define SWZ(o) ((o) ^ (((o) >> 3) & 0x70))

__device__ __forceinline__ uint32_t pack_bf16x2(float lo, float hi) {
    uint32_t r; asm("cvt.rn.bf16x2.f32 %0, %1, %2;" : "=r"(r) : "f"(hi), "f"(lo));
    return r;
}

static constexpr uint32_t IDESC_128x64 =
    (1u << 4) | (1u << 7) | (1u << 10) | ((64u/8) << 17) | ((128u/16) << 24);
#endif  // TCG_OK

__global__ __launch_bounds__(128) void attn_tc_kernel(
    const float* __restrict__ q, const float* __restrict__ k,
    const float* __restrict__ v, const float* __restrict__ cr,
    const int* __restrict__ pos, const unsigned char* __restrict__ mask,
    float* __restrict__ attn, float* __restrict__ x, float* __restrict__ rinv)
{
#if TCG_OK
    extern __shared__ char smem8[];
    const uint32_t sb = smem_u32(smem8);
    const int tid = threadIdx.x;
    const int wid = tid >> 5;
    const int bh = blockIdx.y, b = bh >> 3, h = bh & 7;
    const int i0 = blockIdx.x * 128;
    const int gi = i0 + tid;
    const uint32_t woff = ((uint32_t)wid) << 21;

    if (wid == 0) TCG_ALLOC(sb + SM_TPTR, TM_COLS);
    if (tid == 0) { MBAR_INIT(sb + SM_SBAR, 1); MBAR_INIT(sb + SM_PVBAR, 1); }
    __syncthreads();
    uint32_t tb;
    asm volatile("ld.shared.b32 %0, [%1];" : "=r"(tb) : "r"(sb + SM_TPTR));

    {   // Q tile (128 x 64) -> split bf16, SW128; thread t = row t
        const float* qrow = q + (size_t)(b*SS + gi)*HID + h*DH;
#pragma unroll
        for (int u = 0; u < 16; ++u) {
            float4 a = *(const float4*)(qrow + 4*u);
            uint32_t h01 = pack_bf16x2(a.x, a.y);
            uint32_t h23 = pack_bf16x2(a.z, a.w);
            float r0 = a.x - __uint_as_float(h01 << 16);
            float r1 = a.y - __uint_as_float(h01 & 0xffff0000u);
            float r2 = a.z - __uint_as_float(h23 << 16);
            float r3 = a.w - __uint_as_float(h23 & 0xffff0000u);
            uint32_t o = SWZ((uint32_t)(tid*128 + u*8));
            *(uint2*)(smem8 + SM_QH + o) = make_uint2(h01, h23);
            *(uint2*)(smem8 + SM_QL + o) = make_uint2(pack_bf16x2(r0, r1), pack_bf16x2(r2, r3));
        }
    }
    float c0, c1, c2;
    {
        const float* cp = cr + (size_t)((b*SS + gi)*NH + h)*4;
        c0 = cp[0]; c1 = cp[1]; c2 = cp[2];
    }
    FENCE_ASYNC();

    const uint64_t dQH = MK_DESC(sb + SM_QH), dQL = MK_DESC(sb + SM_QL);
    const uint64_t dKH = MK_DESC(sb + SM_KH), dKL = MK_DESC(sb + SM_KL);
    const uint64_t dVH = MK_DESC(sb + SM_VTH), dVL = MK_DESC(sb + SM_VTL);

    float rsum = 0.f;
    uint32_t sp = 0, pvp = 0;

    for (int t = 0, j0 = 0; j0 < SS; ++t, j0 += 64) {
        if (t > 0) { MBAR_WAIT(sb + SM_PVBAR, pvp); pvp ^= 1; }
        __syncthreads();

        {   // K (64x64) split bf16 + V transposed
            int r = tid >> 1;
            int dc = (tid & 1) * 32;
            const float* krow = k + (size_t)(b*SS + j0 + r)*HID + h*DH + dc;
            const float* vrow = v + (size_t)(b*SS + j0 + r)*HID + h*DH + dc;
#pragma unroll
            for (int u = 0; u < 8; ++u) {
                int d0 = dc + 4*u;
                float4 a = *(const float4*)(krow + 4*u);
                uint32_t h01 = pack_bf16x2(a.x, a.y);
                uint32_t h23 = pack_bf16x2(a.z, a.w);
                float r0 = a.x - __uint_as_float(h01 << 16);
                float r1 = a.y - __uint_as_float(h01 & 0xffff0000u);
                float r2 = a.z - __uint_as_float(h23 << 16);
                float r3 = a.w - __uint_as_float(h23 & 0xffff0000u);
                uint32_t o = SWZ((uint32_t)(r*128 + d0*2));
                *(uint2*)(smem8 + SM_KH + o) = make_uint2(h01, h23);
                *(uint2*)(smem8 + SM_KL + o) =
                    make_uint2(pack_bf16x2(r0, r1), pack_bf16x2(r2, r3));

                float4 vv = *(const float4*)(vrow + 4*u);
                float ve[4] = {vv.x, vv.y, vv.z, vv.w};
#pragma unroll
                for (int e = 0; e < 4; ++e) {
                    int d = d0 + e;
                    __nv_bfloat16 vh = __float2bfloat16(ve[e]);
                    __nv_bfloat16 vl = __float2bfloat16(ve[e] - __bfloat162float(vh));
                    uint32_t ov = SWZ((uint32_t)(d*128 + r*2));
                    *(__nv_bfloat16*)(smem8 + SM_VTH + ov) = vh;
                    *(__nv_bfloat16*)(smem8 + SM_VTL + ov) = vl;
                }
            }
        }
        FENCE_ASYNC();
        __syncthreads();

        // S = QhKh + QhKl + QlKh
        if (wid == 0) {
            if (elect_one_pred()) {
#pragma unroll
                for (int m = 0; m < 3; ++m) {
                    uint64_t ad = (m == 2) ? dQL : dQH;
                    uint64_t bd = (m == 1) ? dKL : dKH;
#pragma unroll
                    for (int ks = 0; ks < 4; ++ks)
                        mma_f16_ss(tb + TM_S, ad + ks*2, bd + ks*2, IDESC_128x64,
                                   !(m == 0 && ks == 0));
                }
                TCG_COMMIT(sb + SM_SBAR);
            }
        }
        MBAR_WAIT(sb + SM_SBAR, sp); sp ^= 1;
        TCG_FENCE_AFTER();

        // epilogue: two halves of 32 cols
#pragma unroll
        for (int hh = 0; hh < 2; ++hh) {
            uint32_t sr[32];
            TCG_LD_X32(sr, tb + TM_S + hh*32);
            TCG_WAIT_LD();
            float p[32];
            const int jc0 = j0 + hh*32;
#pragma unroll
            for (int g = 0; g < 8; ++g) {
                int4 pp = *(const int4*)(pos + (size_t)gi*SS + jc0 + 4*g);
                uchar4 mm = *(const uchar4*)(mask + (size_t)b*SS*SS + (size_t)gi*SS + jc0 + 4*g);
                int pi[4] = {pp.x, pp.y, pp.z, pp.w};
                unsigned char mi[4] = {mm.x, mm.y, mm.z, mm.w};
#pragma unroll
                for (int e = 0; e < 4; ++e) {
                    float bias = (pi[e] == 0) ? c0 : ((pi[e] == 1) ? c1 : c2);
                    float s = (__uint_as_float(sr[4*g + e]) + bias) * 0.125f;
                    float pe = mi[e] ? 0.f : __expf(s);
                    p[4*g + e] = pe;
                    rsum += pe;
                }
                *(float4*)(attn + ((size_t)bh*SS + gi)*SS + jc0 + 4*g) =
                    make_float4(p[4*g], p[4*g+1], p[4*g+2], p[4*g+3]);
            }
            uint32_t ph[16], pl[16];
#pragma unroll
            for (int c = 0; c < 16; ++c) {
                float p0 = p[2*c], p1 = p[2*c+1];
                uint32_t hp = pack_bf16x2(p0, p1);
                ph[c] = hp;
                pl[c] = pack_bf16x2(p0 - __uint_as_float(hp << 16),
                                    p1 - __uint_as_float(hp & 0xffff0000u));
            }
            TCG_ST_X16(tb + TM_PH + hh*16 + woff, ph);
            TCG_ST_X16(tb + TM_PL + hh*16 + woff, pl);
            TCG_WAIT_ST();
        }
        TCG_FENCE_BEFORE();
        __syncthreads();

        // O += PhVh + PhVl + PlVh
        if (wid == 0) {
            if (elect_one_pred()) {
                TCG_FENCE_AFTER();
#pragma unroll
                for (int m = 0; m < 3; ++m) {
                    uint32_t at = tb + ((m == 2) ? TM_PL : TM_PH);
                    uint64_t bd = (m == 1) ? dVL : dVH;
#pragma unroll
                    for (int ks = 0; ks < 4; ++ks)
                        mma_f16_ts(tb + TM_O, at + ks*8, bd + ks*2, IDESC_128x64,
                                   !(t == 0 && m == 0 && ks == 0));
                }
                TCG_COMMIT(sb + SM_PVBAR);
            }
        }
    }

    MBAR_WAIT(sb + SM_PVBAR, pvp);
    TCG_FENCE_AFTER();

    {
        float inv = 1.0f / rsum;
        rinv[(size_t)bh*SS + gi] = inv;
        float* xrow = x + (size_t)(b*SS + gi)*HID + h*DH;
#pragma unroll
        for (int hh = 0; hh < 2; ++hh) {
            uint32_t orw[32];
            TCG_LD_X32(orw, tb + TM_O + hh*32);
            TCG_WAIT_LD();
#pragma unroll
            for (int g = 0; g < 8; ++g) {
                float4 ov = make_float4(__uint_as_float(orw[4*g+0]) * inv,
                                        __uint_as_float(orw[4*g+1]) * inv,
                                        __uint_as_float(orw[4*g+2]) * inv,
                                        __uint_as_float(orw[4*g+3]) * inv);
                *(float4*)(xrow + hh*32 + 4*g) = ov;
            }
        }
    }

    __syncthreads();
    if (tid == 0) { MBAR_INVAL(sb + SM_SBAR); MBAR_INVAL(sb + SM_PVBAR); }
    __syncthreads();
    if (wid == 0) TCG_DEALLOC(tb, TM_COLS);
#endif  // TCG_OK
}

// ===========================================================================
// SIMT fallback attention (Round-4 passing kernel). Real body ONLY in the
// generic (non-'a') device pass; empty in the sm_103a pass. Exactly one of
// {attn_tc_kernel, attn_simt_kernel} does work in whichever cubin loads.
// ===========================================================================
__global__ __launch_bounds__(256) void attn_simt_kernel(
    const float* __restrict__ q, const float* __restrict__ k,
    const float* __restrict__ v, const float* __restrict__ cr,
    const int* __restrict__ pos, const unsigned char* __restrict__ mask,
    float* __restrict__ attn, float* __restrict__ x, float* __restrict__ rinv)
{
#if !TCG_OK
    extern __shared__ float sm[];
    float* Qt   = sm;
    float* KtPt = sm + 4160;
    float* Vs   = sm + 8320;
    float* crs  = sm + 12416;

    const int tid = threadIdx.x;
    const int tx = tid & 15, ty = tid >> 4;
    const int bh = blockIdx.y, b = bh >> 3, h = bh & 7;
    const int i0 = blockIdx.x * 64;
    const int iy = ty * 4;

#pragma unroll
    for (int pass = 0; pass < 4; ++pass) {
        int idx = pass*256 + tid;
        int i = idx >> 4, d = (idx & 15) << 2;
        float4 qv = *(const float4*)(q + (size_t)(b*SS + i0 + i)*HID + h*DH + d);
        Qt[(d+0)*65 + i] = qv.x; Qt[(d+1)*65 + i] = qv.y;
        Qt[(d+2)*65 + i] = qv.z; Qt[(d+3)*65 + i] = qv.w;
    }
    {
        int i = tid >> 2, r = tid & 3;
        crs[i*4 + r] = cr[(size_t)((b*SS + i0 + i)*NH + h)*4 + r];
    }

    float o[4][4] = {};
    float rsum[4] = {};

    for (int j0 = 0; j0 < SS; j0 += 64) {
        __syncthreads();
#pragma unroll
        for (int pass = 0; pass < 4; ++pass) {
            int idx = pass*256 + tid;
            int j = idx >> 4, d = (idx & 15) << 2;
            size_t goff = (size_t)(b*SS + j0 + j)*HID + h*DH + d;
            float4 kv = *(const float4*)(k + goff);
            KtPt[(d+0)*65 + j] = kv.x; KtPt[(d+1)*65 + j] = kv.y;
            KtPt[(d+2)*65 + j] = kv.z; KtPt[(d+3)*65 + j] = kv.w;
            *(float4*)(Vs + j*64 + d) = *(const float4*)(v + goff);
        }
        __syncthreads();

        float acc[4][4] = {};
#pragma unroll
        for (int kk = 0; kk < 64; ++kk) {
            float a[4];
#pragma unroll
            for (int r = 0; r < 4; ++r) a[r] = Qt[kk*65 + iy + r];
            float bvv[4];
#pragma unroll
            for (int c = 0; c < 4; ++c) bvv[c] = KtPt[kk*65 + tx*4 + c];
#pragma unroll
            for (int r = 0; r < 4; ++r)
#pragma unroll
                for (int c = 0; c < 4; ++c) acc[r][c] += a[r] * bvv[c];
        }

        const int jc = j0 + tx*4;
#pragma unroll
        for (int r = 0; r < 4; ++r) {
            int gi = i0 + iy + r;
            int4 pp = *(const int4*)(pos + (size_t)gi*SS + jc);
            uchar4 mm = *(const uchar4*)(mask + (size_t)b*SS*SS + (size_t)gi*SS + jc);
            const float* cp = crs + (iy + r)*4;
            float s0 = (acc[r][0] + cp[pp.x]) * 0.125f;
            float s1 = (acc[r][1] + cp[pp.y]) * 0.125f;
            float s2 = (acc[r][2] + cp[pp.z]) * 0.125f;
            float s3 = (acc[r][3] + cp[pp.w]) * 0.125f;
            float p0 = mm.x ? 0.f : expf(s0);
            float p1 = mm.y ? 0.f : expf(s1);
            float p2 = mm.z ? 0.f : expf(s2);
            float p3 = mm.w ? 0.f : expf(s3);
            rsum[r] += (p0 + p1) + (p2 + p3);
            *(float4*)(attn + ((size_t)bh*SS + gi)*SS + jc) = make_float4(p0, p1, p2, p3);
            acc[r][0] = p0; acc[r][1] = p1; acc[r][2] = p2; acc[r][3] = p3;
        }

        __syncthreads();
#pragma unroll
        for (int r = 0; r < 4; ++r)
#pragma unroll
            for (int c = 0; c < 4; ++c)
                KtPt[(tx*4 + c)*65 + iy + r] = acc[r][c];
        __syncthreads();

#pragma unroll
        for (int kk = 0; kk < 64; ++kk) {
            float p[4];
#pragma unroll
            for (int r = 0; r < 4; ++r) p[r] = KtPt[kk*65 + iy + r];
            float4 vv = *(float4*)(Vs + kk*64 + tx*4);
            float vvv[4] = {vv.x, vv.y, vv.z, vv.w};
#pragma unroll
            for (int r = 0; r < 4; ++r)
#pragma unroll
                for (int c = 0; c < 4; ++c) o[r][c] += p[r] * vvv[c];
        }
    }

#pragma unroll
    for (int r = 0; r < 4; ++r) {
        float s = rsum[r];
        s += __shfl_xor_sync(0xffffffffu, s, 8, 16);
        s += __shfl_xor_sync(0xffffffffu, s, 4, 16);
        s += __shfl_xor_sync(0xffffffffu, s, 2, 16);
        s += __shfl_xor_sync(0xffffffffu, s, 1, 16);
        rsum[r] = 1.0f / s;
    }
    if (tx == 0) {
#pragma unroll
        for (int r = 0; r < 4; ++r)
            rinv[(size_t)bh*SS + i0 + iy + r] = rsum[r];
    }
#pragma unroll
    for (int r = 0; r < 4; ++r) {
        float4 ov = make_float4(o[r][0]*rsum[r], o[r][1]*rsum[r],
                                o[r][2]*rsum[r], o[r][3]*rsum[r]);
        *(float4*)(x + (size_t)(b*SS + i0 + iy + r)*HID + h*DH + tx*4) = ov;
    }
#endif  // !TCG_OK
}

// ===========================================================================
// Normalize attn rows
// ===========================================================================
__global__ void norm_kernel(float* __restrict__ attn, const float* __restrict__ rinv)
{
    const size_t n4 = (size_t)BB*NH*SS*SS/4;
    for (size_t idx = (size_t)blockIdx.x*blockDim.x + threadIdx.x; idx < n4;
         idx += (size_t)gridDim.x*blockDim.x) {
        float inv = rinv[idx >> 9];
        float4 v = ((const float4*)attn)[idx];
        v.x *= inv; v.y *= inv; v.z *= inv; v.w *= inv;
        ((float4*)attn)[idx] = v;
    }
}

// ===========================================================================
extern "C" void kernel_launch(void* const* d_in, const int* in_sizes, int n_in,
                              void* d_out, int out_size)
{
    const float* query = (const float*)d_in[0];
    const float* key_  = (const float*)d_in[1];
    const float* value = (const float*)d_in[2];
    const unsigned char* mask = (const unsigned char*)d_in[3];
    const int*   pos   = (const int*)d_in[4];
    const float* Wq = (const float*)d_in[5];
    const float* bq = (const float*)d_in[6];
    const float* Wk = (const float*)d_in[7];
    const float* bk = (const float*)d_in[8];
    const float* Wv = (const float*)d_in[9];
    const float* bv = (const float*)d_in[10];
    const float* Wo = (const float*)d_in[11];
    const float* bo = (const float*)d_in[12];
    const float* rel = (const float*)d_in[13];

    float* out  = (float*)d_out;                     // (B,S,HID)
    float* attn = out + (size_t)BSROWS*HID;          // (B,H,S,S)

    float *qb, *kb, *vb, *xb, *crb, *rb;
    cudaGetSymbolAddress((void**)&qb, g_q);
    cudaGetSymbolAddress((void**)&kb, g_k);
    cudaGetSymbolAddress((void**)&vb, g_v);
    cudaGetSymbolAddress((void**)&xb, g_x);
    cudaGetSymbolAddress((void**)&crb, g_cr);
    cudaGetSymbolAddress((void**)&rb, g_rinv);

    cudaFuncSetAttribute(attn_tc_kernel,
                         cudaFuncAttributeMaxDynamicSharedMemorySize, SM_TOTAL);
    const int simt_smem = 12672 * 4;
    cudaFuncSetAttribute(attn_simt_kernel,
                         cudaFuncAttributeMaxDynamicSharedMemorySize, simt_smem);

    dim3 gemm_grid(HID/64, BSROWS/64);   // (8, 64)
    gemm_bias_kernel<<<gemm_grid, 256>>>(query, Wq, bq, qb);
    gemm_bias_kernel<<<gemm_grid, 256>>>(key_,  Wk, bk, kb);
    gemm_bias_kernel<<<gemm_grid, 256>>>(value, Wv, bv, vb);

    cr_kernel<<<(BSROWS*NH*32 + 255)/256, 256>>>(qb, kb, rel, crb);

    // Exactly one of these has a non-empty body in the loaded cubin.
    attn_tc_kernel<<<dim3(SS/128, BB*NH), 128, SM_TOTAL>>>(
        qb, kb, vb, crb, pos, mask, attn, xb, rb);
    attn_simt_kernel<<<dim3(SS/64, BB*NH), 256, simt_smem>>>(
        qb, kb, vb, crb, pos, mask, attn, xb, rb);

    norm_kernel<<<2048, 256>>>(attn, rb);

    gemm_bias_kernel<<<gemm_grid, 256>>>(xb, Wo, bo, out);
}

// round 7
// speedup vs baseline: 1.2678x; 1.1461x over previous
#include <cuda_runtime.h>
#include <cuda_bf16.h>
#include <cstdint>
#include <cstddef>

#define BB 2
#define SS 2048
#define HID 512
#define NH 8
#define DH 64
#define BSROWS (BB*SS)   // 4096

// tcgen05 is arch-SPECIFIC: only emit in sm_103a/sm_100a passes, never the
// generic compute_103 pass (ptxas rejects it there — Round-5 failure).
// Round-6 rel_err fingerprint PROVED the arch-specific cubin is what loads.
#if defined(__CUDA_ARCH_FEAT_SM103_ALL) || defined(__CUDA_ARCH_FEAT_SM100_ALL) || \
    (defined(__CUDA_ARCH_SPECIFIC__) && (__CUDA_ARCH_SPECIFIC__ >= 1000))
#define TCG_OK 1
#else
#define TCG_OK 0
#endif

// Scratch (device globals — allocation-free rule)
__device__ __align__(16) float g_q[BSROWS*HID];
__device__ __align__(16) float g_k[BSROWS*HID];
__device__ __align__(16) float g_v[BSROWS*HID];
__device__ __align__(16) float g_x[BSROWS*HID];
__device__ __align__(16) float g_cr[BSROWS*NH*4];
__device__ __align__(16) float g_rinv[BB*NH*SS];
__device__ __align__(16) __nv_bfloat16 g_wth[4*HID*HID];  // Wt[n,k] hi, 4 matrices
__device__ __align__(16) __nv_bfloat16 g_wtl[4*HID*HID];  // Wt[n,k] lo

// ===========================================================================
// PTX helpers (arch-specific passes only)
// ===========================================================================
#if TCG_OK
__device__ __forceinline__ uint32_t elect_one_pred() {
    uint32_t pred;
    asm volatile("{\n\t.reg .pred p;\n\telect.sync _|p, 0xFFFFFFFF;\n\t"
                 "selp.b32 %0, 1, 0, p;\n\t}" : "=r"(pred));
    return pred;
}
__device__ __forceinline__ uint32_t smem_u32(const void* p) {
    uint32_t a;
    asm("{ .reg .u64 t; cvta.to.shared.u64 t, %1; cvt.u32.u64 %0, t; }"
        : "=r"(a) : "l"(p));
    return a;
}
#define TCG_ALLOC(sa, n)   asm volatile("tcgen05.alloc.cta_group::1.sync.aligned.shared::cta.b32 [%0], %1;" :: "r"((uint32_t)(sa)), "r"((uint32_t)(n)) : "memory")
#define TCG_DEALLOC(t, n)  asm volatile("tcgen05.dealloc.cta_group::1.sync.aligned.b32 %0, %1;" :: "r"(t), "r"((uint32_t)(n)))
#define TCG_WAIT_LD()      asm volatile("tcgen05.wait::ld.sync.aligned;" ::: "memory")
#define TCG_WAIT_ST()      asm volatile("tcgen05.wait::st.sync.aligned;" ::: "memory")
#define TCG_FENCE_BEFORE() asm volatile("tcgen05.fence::before_thread_sync;" ::: "memory")
#define TCG_FENCE_AFTER()  asm volatile("tcgen05.fence::after_thread_sync;" ::: "memory")
#define TCG_COMMIT(mb)     asm volatile("tcgen05.commit.cta_group::1.mbarrier::arrive::one.shared::cluster.b64 [%0];" :: "r"((uint32_t)(mb)) : "memory")
#define FENCE_ASYNC()      asm volatile("fence.proxy.async.shared::cta;" ::: "memory")
#define MBAR_INIT(mb, c)   asm volatile("mbarrier.init.shared.b64 [%0], %1;" :: "r"((uint32_t)(mb)), "r"((uint32_t)(c)) : "memory")
#define MBAR_INVAL(mb)     asm volatile("mbarrier.inval.shared.b64 [%0];" :: "r"((uint32_t)(mb)) : "memory")

#define MBAR_WAIT(mb, ph) do { \
    uint32_t _m = (uint32_t)(mb), _p = (uint32_t)(ph), _d; \
    asm volatile("{\n\t.reg .pred p;\n\t" \
        "mbarrier.try_wait.parity.acquire.cta.shared::cta.b64 p, [%1], %2;\n\t" \
        "selp.b32 %0, 1, 0, p;\n\t}" : "=r"(_d) : "r"(_m), "r"(_p) : "memory"); \
    if (!_d) { \
        asm volatile("{\n\t.reg .pred P1;\n\t" \
            "WL_%=:\n\t" \
            "mbarrier.try_wait.parity.acquire.cta.shared::cta.b64 P1, [%0], %1, 0x989680;\n\t" \
            "@P1 bra.uni WD_%=;\n\t" \
            "bra.uni WL_%=;\n\t" \
            "WD_%=:\n\t}" :: "r"(_m), "r"(_p) : "memory"); \
    } \
} while (0)

#define TCG_LD_X32(r, ta) \
    asm volatile("tcgen05.ld.sync.aligned.32x32b.x32.b32 " \
        "{%0, %1, %2, %3, %4, %5, %6, %7, %8, %9, %10, %11, %12, %13, %14, %15, " \
        " %16, %17, %18, %19, %20, %21, %22, %23, %24, %25, %26, %27, %28, %29, %30, %31}, [%32];" \
        : "=r"((r)[0]),  "=r"((r)[1]),  "=r"((r)[2]),  "=r"((r)[3]), \
          "=r"((r)[4]),  "=r"((r)[5]),  "=r"((r)[6]),  "=r"((r)[7]), \
          "=r"((r)[8]),  "=r"((r)[9]),  "=r"((r)[10]), "=r"((r)[11]), \
          "=r"((r)[12]), "=r"((r)[13]), "=r"((r)[14]), "=r"((r)[15]), \
          "=r"((r)[16]), "=r"((r)[17]), "=r"((r)[18]), "=r"((r)[19]), \
          "=r"((r)[20]), "=r"((r)[21]), "=r"((r)[22]), "=r"((r)[23]), \
          "=r"((r)[24]), "=r"((r)[25]), "=r"((r)[26]), "=r"((r)[27]), \
          "=r"((r)[28]), "=r"((r)[29]), "=r"((r)[30]), "=r"((r)[31]) \
        : "r"(ta))

#define TCG_ST_X16(ta, r) \
    asm volatile("tcgen05.st.sync.aligned.32x32b.x16.b32 [%0], " \
        "{%1, %2, %3, %4, %5, %6, %7, %8, %9, %10, %11, %12, %13, %14, %15, %16};" \
        :: "r"(ta), \
           "r"((r)[0]),  "r"((r)[1]),  "r"((r)[2]),  "r"((r)[3]), \
           "r"((r)[4]),  "r"((r)[5]),  "r"((r)[6]),  "r"((r)[7]), \
           "r"((r)[8]),  "r"((r)[9]),  "r"((r)[10]), "r"((r)[11]), \
           "r"((r)[12]), "r"((r)[13]), "r"((r)[14]), "r"((r)[15]) \
        : "memory")

__device__ __forceinline__ void mma_f16_ss(uint32_t d_tmem, uint64_t a_desc,
                                           uint64_t b_desc, uint32_t idesc, bool acc) {
    uint32_t en = acc ? 1u : 0u;
    asm volatile("{\n\t.reg .pred p;\n\tsetp.ne.u32 p, %5, 0;\n\t"
        "tcgen05.mma.cta_group::1.kind::f16 [%0], %1, %2, %3, {%4, %4, %4, %4}, p;\n\t}"
        :: "r"(d_tmem), "l"(a_desc), "l"(b_desc), "r"(idesc), "r"(0u), "r"(en) : "memory");
}
__device__ __forceinline__ void mma_f16_ts(uint32_t d_tmem, uint32_t a_tmem,
                                           uint64_t b_desc, uint32_t idesc, bool acc) {
    uint32_t en = acc ? 1u : 0u;
    asm volatile("{\n\t.reg .pred p;\n\tsetp.ne.u32 p, %5, 0;\n\t"
        "tcgen05.mma.cta_group::1.kind::f16 [%0], [%1], %2, %3, {%4, %4, %4, %4}, p;\n\t}"
        :: "r"(d_tmem), "r"(a_tmem), "l"(b_desc), "r"(idesc), "r"(0u), "r"(en) : "memory");
}

static constexpr uint64_t SMEM_DESC_BASE_SW128 =
    (uint64_t(2) << 61) | (uint64_t(1) << 46) | (uint64_t(64) << 32) | (uint64_t(1) << 16);
#define MK_DESC(a) (SMEM_DESC_BASE_SW128 | ((uint64_t)((a) >> 4) & 0x3FFF))
#define SWZ(o) ((o) ^ (((o) >> 3) & 0x70))

__device__ __forceinline__ uint32_t pack_bf16x2(float lo, float hi) {
    uint32_t r; asm("cvt.rn.bf16x2.f32 %0, %1, %2;" : "=r"(r) : "f"(hi), "f"(lo));
    return r;
}

static constexpr uint32_t IDESC_128x64 =
    (1u << 4) | (1u << 7) | (1u << 10) | ((64u/8) << 17) | ((128u/16) << 24);
static constexpr uint32_t IDESC_128x128 =
    (1u << 4) | (1u << 7) | (1u << 10) | ((128u/8) << 17) | ((128u/16) << 24);
#endif  // TCG_OK

// ===========================================================================
// Weight prep: Wt[n,k] (hi/lo bf16) = transpose+split of W[k,n], all 4 mats.
// grid (16,16,4), block (32,8).
// ===========================================================================
__global__ void wprep_kernel(const float* __restrict__ W0, const float* __restrict__ W1,
                             const float* __restrict__ W2, const float* __restrict__ W3,
                             __nv_bfloat16* __restrict__ wth, __nv_bfloat16* __restrict__ wtl)
{
    __shared__ float tile[32][33];
    const int z = blockIdx.z;
    const float* W = (z == 0) ? W0 : (z == 1) ? W1 : (z == 2) ? W2 : W3;
    const int n0 = blockIdx.x * 32, k0 = blockIdx.y * 32;
    const int tx = threadIdx.x, ty = threadIdx.y;
#pragma unroll
    for (int i = ty; i < 32; i += 8)
        tile[i][tx] = W[(size_t)(k0 + i)*HID + n0 + tx];   // tile[k][n]
    __syncthreads();
#pragma unroll
    for (int i = ty; i < 32; i += 8) {
        float v = tile[tx][i];                             // W[k0+tx][n0+i]
        __nv_bfloat16 h = __float2bfloat16(v);
        __nv_bfloat16 l = __float2bfloat16(v - __bfloat162float(h));
        size_t o = (size_t)z*HID*HID + (size_t)(n0 + i)*HID + k0 + tx;
        wth[o] = h; wtl[o] = l;
    }
}

// ===========================================================================
// tcgen05 GEMM: C[4096,512] = A @ W + bias, W pre-transposed+split.
// CTA = 128x128 C tile, 128 threads, 8 K-chunks of 64, split-bf16 (3 MMAs).
// ===========================================================================
#define GM_TPTR   0
#define GM_BAR    8
#define GM_AH     1024
#define GM_AL     17408
#define GM_BH     33792
#define GM_BL     50176
#define GM_TOTAL  66560

__global__ __launch_bounds__(128) void gemm_tc_kernel(
    const float* __restrict__ A,
    const __nv_bfloat16* __restrict__ Wth, const __nv_bfloat16* __restrict__ Wtl,
    const float* __restrict__ bias, float* __restrict__ C)
{
#if TCG_OK
    extern __shared__ char smem8[];
    const uint32_t sb = smem_u32(smem8);
    const int tid = threadIdx.x;
    const int wid = tid >> 5;
    const int row0 = blockIdx.y * 128, col0 = blockIdx.x * 128;

    if (wid == 0) TCG_ALLOC(sb + GM_TPTR, 128);
    if (tid == 0) MBAR_INIT(sb + GM_BAR, 1);
    __syncthreads();
    uint32_t tb;
    asm volatile("ld.shared.b32 %0, [%1];" : "=r"(tb) : "r"(sb + GM_TPTR));

    const uint64_t dAH = MK_DESC(sb + GM_AH), dAL = MK_DESC(sb + GM_AL);
    const uint64_t dBH = MK_DESC(sb + GM_BH), dBL = MK_DESC(sb + GM_BL);

    uint32_t sp = 0;
    for (int ch = 0; ch < 8; ++ch) {
        if (ch > 0) { MBAR_WAIT(sb + GM_BAR, sp); sp ^= 1; }
        __syncthreads();

        {   // A tile: row tid, 64 floats -> split bf16, SW128
            const float* arow = A + (size_t)(row0 + tid)*HID + ch*64;
#pragma unroll
            for (int u = 0; u < 16; ++u) {
                float4 a = *(const float4*)(arow + 4*u);
                uint32_t h01 = pack_bf16x2(a.x, a.y);
                uint32_t h23 = pack_bf16x2(a.z, a.w);
                float r0 = a.x - __uint_as_float(h01 << 16);
                float r1 = a.y - __uint_as_float(h01 & 0xffff0000u);
                float r2 = a.z - __uint_as_float(h23 << 16);
                float r3 = a.w - __uint_as_float(h23 & 0xffff0000u);
                uint32_t o = SWZ((uint32_t)(tid*128 + u*8));
                *(uint2*)(smem8 + GM_AH + o) = make_uint2(h01, h23);
                *(uint2*)(smem8 + GM_AL + o) = make_uint2(pack_bf16x2(r0, r1), pack_bf16x2(r2, r3));
            }
        }
        {   // W tiles: row n = tid, 64 bf16 = 128B, vectorized copy, SW128
            const uint4* bh = (const uint4*)(Wth + (size_t)(col0 + tid)*HID + ch*64);
            const uint4* bl = (const uint4*)(Wtl + (size_t)(col0 + tid)*HID + ch*64);
#pragma unroll
            for (int u = 0; u < 8; ++u) {
                uint32_t o = SWZ((uint32_t)(tid*128 + u*16));
                *(uint4*)(smem8 + GM_BH + o) = bh[u];
                *(uint4*)(smem8 + GM_BL + o) = bl[u];
            }
        }
        FENCE_ASYNC();
        __syncthreads();

        if (wid == 0) {
            if (elect_one_pred()) {
#pragma unroll
                for (int m = 0; m < 3; ++m) {
                    uint64_t ad = (m == 2) ? dAL : dAH;
                    uint64_t bd = (m == 1) ? dBL : dBH;
#pragma unroll
                    for (int ks = 0; ks < 4; ++ks)
                        mma_f16_ss(tb, ad + ks*2, bd + ks*2, IDESC_128x128,
                                   !(ch == 0 && m == 0 && ks == 0));
                }
                TCG_COMMIT(sb + GM_BAR);
            }
        }
    }
    MBAR_WAIT(sb + GM_BAR, sp);
    TCG_FENCE_AFTER();

    // epilogue: D(row=tid, 128 cols) + bias -> C
    {
        float* crow = C + (size_t)(row0 + tid)*HID + col0;
#pragma unroll
        for (int hh = 0; hh < 4; ++hh) {
            uint32_t dr[32];
            TCG_LD_X32(dr, tb + hh*32);
            TCG_WAIT_LD();
#pragma unroll
            for (int g = 0; g < 8; ++g) {
                float4 bv = *(const float4*)(bias + col0 + hh*32 + 4*g);
                float4 o = make_float4(__uint_as_float(dr[4*g+0]) + bv.x,
                                       __uint_as_float(dr[4*g+1]) + bv.y,
                                       __uint_as_float(dr[4*g+2]) + bv.z,
                                       __uint_as_float(dr[4*g+3]) + bv.w);
                *(float4*)(crow + hh*32 + 4*g) = o;
            }
        }
    }

    __syncthreads();
    if (tid == 0) MBAR_INVAL(sb + GM_BAR);
    __syncthreads();
    if (wid == 0) TCG_DEALLOC(tb, 128);
#endif  // TCG_OK
}

// ===========================================================================
// cr_kernel (unchanged)
// ===========================================================================
__global__ void cr_kernel(const float* __restrict__ q, const float* __restrict__ k,
                          const float* __restrict__ rel, float* __restrict__ cr)
{
    int gw = (int)((blockIdx.x * blockDim.x + threadIdx.x) >> 5);
    int lane = threadIdx.x & 31;
    if (gw >= BSROWS*NH) return;
    int row = gw >> 3, h = gw & 7;
    const float* qp = q + (size_t)row*HID + h*DH;
    const float* kp = k + (size_t)row*HID + h*DH;
    float2 qv = *(const float2*)(qp + lane*2);
    float2 kv = *(const float2*)(kp + lane*2);
    float a0 = qv.x + kv.x, a1 = qv.y + kv.y;
#pragma unroll
    for (int r = 0; r < 3; ++r) {
        float2 rv = *(const float2*)(rel + r*DH + lane*2);
        float s = a0*rv.x + a1*rv.y;
        s += __shfl_xor_sync(0xffffffffu, s, 16);
        s += __shfl_xor_sync(0xffffffffu, s, 8);
        s += __shfl_xor_sync(0xffffffffu, s, 4);
        s += __shfl_xor_sync(0xffffffffu, s, 2);
        s += __shfl_xor_sync(0xffffffffu, s, 1);
        if (lane == 0) cr[(size_t)gw*4 + r] = s;
    }
    if (lane == 0) cr[(size_t)gw*4 + 3] = 0.f;
}

// ===========================================================================
// tcgen05 attention (unchanged from Round-6 passing kernel)
// ===========================================================================
#define SM_TPTR   0
#define SM_SBAR   8
#define SM_PVBAR  16
#define SM_QH     1024
#define SM_QL     17408
#define SM_KH     33792
#define SM_KL     41984
#define SM_VTH    50176
#define SM_VTL    58368
#define SM_TOTAL  66560

#define TM_S   0
#define TM_O   64
#define TM_PH  128
#define TM_PL  160
#define TM_COLS 256

__global__ __launch_bounds__(128) void attn_tc_kernel(
    const float* __restrict__ q, const float* __restrict__ k,
    const float* __restrict__ v, const float* __restrict__ cr,
    const int* __restrict__ pos, const unsigned char* __restrict__ mask,
    float* __restrict__ attn, float* __restrict__ x, float* __restrict__ rinv)
{
#if TCG_OK
    extern __shared__ char smem8[];
    const uint32_t sb = smem_u32(smem8);
    const int tid = threadIdx.x;
    const int wid = tid >> 5;
    const int bh = blockIdx.y, b = bh >> 3, h = bh & 7;
    const int i0 = blockIdx.x * 128;
    const int gi = i0 + tid;
    const uint32_t woff = ((uint32_t)wid) << 21;

    if (wid == 0) TCG_ALLOC(sb + SM_TPTR, TM_COLS);
    if (tid == 0) { MBAR_INIT(sb + SM_SBAR, 1); MBAR_INIT(sb + SM_PVBAR, 1); }
    __syncthreads();
    uint32_t tb;
    asm volatile("ld.shared.b32 %0, [%1];" : "=r"(tb) : "r"(sb + SM_TPTR));

    {   // Q tile (128 x 64) -> split bf16, SW128; thread t = row t
        const float* qrow = q + (size_t)(b*SS + gi)*HID + h*DH;
#pragma unroll
        for (int u = 0; u < 16; ++u) {
            float4 a = *(const float4*)(qrow + 4*u);
            uint32_t h01 = pack_bf16x2(a.x, a.y);
            uint32_t h23 = pack_bf16x2(a.z, a.w);
            float r0 = a.x - __uint_as_float(h01 << 16);
            float r1 = a.y - __uint_as_float(h01 & 0xffff0000u);
            float r2 = a.z - __uint_as_float(h23 << 16);
            float r3 = a.w - __uint_as_float(h23 & 0xffff0000u);
            uint32_t o = SWZ((uint32_t)(tid*128 + u*8));
            *(uint2*)(smem8 + SM_QH + o) = make_uint2(h01, h23);
            *(uint2*)(smem8 + SM_QL + o) = make_uint2(pack_bf16x2(r0, r1), pack_bf16x2(r2, r3));
        }
    }
    float c0, c1, c2;
    {
        const float* cp = cr + (size_t)((b*SS + gi)*NH + h)*4;
        c0 = cp[0]; c1 = cp[1]; c2 = cp[2];
    }
    FENCE_ASYNC();

    const uint64_t dQH = MK_DESC(sb + SM_QH), dQL = MK_DESC(sb + SM_QL);
    const uint64_t dKH = MK_DESC(sb + SM_KH), dKL = MK_DESC(sb + SM_KL);
    const uint64_t dVH = MK_DESC(sb + SM_VTH), dVL = MK_DESC(sb + SM_VTL);

    float rsum = 0.f;
    uint32_t sp = 0, pvp = 0;

    for (int t = 0, j0 = 0; j0 < SS; ++t, j0 += 64) {
        if (t > 0) { MBAR_WAIT(sb + SM_PVBAR, pvp); pvp ^= 1; }
        __syncthreads();

        {   // K (64x64) split bf16 + V transposed
            int r = tid >> 1;
            int dc = (tid & 1) * 32;
            const float* krow = k + (size_t)(b*SS + j0 + r)*HID + h*DH + dc;
            const float* vrow = v + (size_t)(b*SS + j0 + r)*HID + h*DH + dc;
#pragma unroll
            for (int u = 0; u < 8; ++u) {
                int d0 = dc + 4*u;
                float4 a = *(const float4*)(krow + 4*u);
                uint32_t h01 = pack_bf16x2(a.x, a.y);
                uint32_t h23 = pack_bf16x2(a.z, a.w);
                float r0 = a.x - __uint_as_float(h01 << 16);
                float r1 = a.y - __uint_as_float(h01 & 0xffff0000u);
                float r2 = a.z - __uint_as_float(h23 << 16);
                float r3 = a.w - __uint_as_float(h23 & 0xffff0000u);
                uint32_t o = SWZ((uint32_t)(r*128 + d0*2));
                *(uint2*)(smem8 + SM_KH + o) = make_uint2(h01, h23);
                *(uint2*)(smem8 + SM_KL + o) =
                    make_uint2(pack_bf16x2(r0, r1), pack_bf16x2(r2, r3));

                float4 vv = *(const float4*)(vrow + 4*u);
                float ve[4] = {vv.x, vv.y, vv.z, vv.w};
#pragma unroll
                for (int e = 0; e < 4; ++e) {
                    int d = d0 + e;
                    __nv_bfloat16 vh = __float2bfloat16(ve[e]);
                    __nv_bfloat16 vl = __float2bfloat16(ve[e] - __bfloat162float(vh));
                    uint32_t ov = SWZ((uint32_t)(d*128 + r*2));
                    *(__nv_bfloat16*)(smem8 + SM_VTH + ov) = vh;
                    *(__nv_bfloat16*)(smem8 + SM_VTL + ov) = vl;
                }
            }
        }
        FENCE_ASYNC();
        __syncthreads();

        // S = QhKh + QhKl + QlKh
        if (wid == 0) {
            if (elect_one_pred()) {
#pragma unroll
                for (int m = 0; m < 3; ++m) {
                    uint64_t ad = (m == 2) ? dQL : dQH;
                    uint64_t bd = (m == 1) ? dKL : dKH;
#pragma unroll
                    for (int ks = 0; ks < 4; ++ks)
                        mma_f16_ss(tb + TM_S, ad + ks*2, bd + ks*2, IDESC_128x64,
                                   !(m == 0 && ks == 0));
                }
                TCG_COMMIT(sb + SM_SBAR);
            }
        }
        MBAR_WAIT(sb + SM_SBAR, sp); sp ^= 1;
        TCG_FENCE_AFTER();

        // epilogue: two halves of 32 cols
#pragma unroll
        for (int hh = 0; hh < 2; ++hh) {
            uint32_t sr[32];
            TCG_LD_X32(sr, tb + TM_S + hh*32);
            TCG_WAIT_LD();
            float p[32];
            const int jc0 = j0 + hh*32;
#pragma unroll
            for (int g = 0; g < 8; ++g) {
                int4 pp = *(const int4*)(pos + (size_t)gi*SS + jc0 + 4*g);
                uchar4 mm = *(const uchar4*)(mask + (size_t)b*SS*SS + (size_t)gi*SS + jc0 + 4*g);
                int pi[4] = {pp.x, pp.y, pp.z, pp.w};
                unsigned char mi[4] = {mm.x, mm.y, mm.z, mm.w};
#pragma unroll
                for (int e = 0; e < 4; ++e) {
                    float bias = (pi[e] == 0) ? c0 : ((pi[e] == 1) ? c1 : c2);
                    float s = (__uint_as_float(sr[4*g + e]) + bias) * 0.125f;
                    float pe = mi[e] ? 0.f : __expf(s);
                    p[4*g + e] = pe;
                    rsum += pe;
                }
                *(float4*)(attn + ((size_t)bh*SS + gi)*SS + jc0 + 4*g) =
                    make_float4(p[4*g], p[4*g+1], p[4*g+2], p[4*g+3]);
            }
            uint32_t ph[16], pl[16];
#pragma unroll
            for (int c = 0; c < 16; ++c) {
                float p0 = p[2*c], p1 = p[2*c+1];
                uint32_t hp = pack_bf16x2(p0, p1);
                ph[c] = hp;
                pl[c] = pack_bf16x2(p0 - __uint_as_float(hp << 16),
                                    p1 - __uint_as_float(hp & 0xffff0000u));
            }
            TCG_ST_X16(tb + TM_PH + hh*16 + woff, ph);
            TCG_ST_X16(tb + TM_PL + hh*16 + woff, pl);
            TCG_WAIT_ST();
        }
        TCG_FENCE_BEFORE();
        __syncthreads();

        // O += PhVh + PhVl + PlVh
        if (wid == 0) {
            if (elect_one_pred()) {
                TCG_FENCE_AFTER();
#pragma unroll
                for (int m = 0; m < 3; ++m) {
                    uint32_t at = tb + ((m == 2) ? TM_PL : TM_PH);
                    uint64_t bd = (m == 1) ? dVL : dVH;
#pragma unroll
                    for (int ks = 0; ks < 4; ++ks)
                        mma_f16_ts(tb + TM_O, at + ks*8, bd + ks*2, IDESC_128x64,
                                   !(t == 0 && m == 0 && ks == 0));
                }
                TCG_COMMIT(sb + SM_PVBAR);
            }
        }
    }

    MBAR_WAIT(sb + SM_PVBAR, pvp);
    TCG_FENCE_AFTER();

    {
        float inv = 1.0f / rsum;
        rinv[(size_t)bh*SS + gi] = inv;
        float* xrow = x + (size_t)(b*SS + gi)*HID + h*DH;
#pragma unroll
        for (int hh = 0; hh < 2; ++hh) {
            uint32_t orw[32];
            TCG_LD_X32(orw, tb + TM_O + hh*32);
            TCG_WAIT_LD();
#pragma unroll
            for (int g = 0; g < 8; ++g) {
                float4 ov = make_float4(__uint_as_float(orw[4*g+0]) * inv,
                                        __uint_as_float(orw[4*g+1]) * inv,
                                        __uint_as_float(orw[4*g+2]) * inv,
                                        __uint_as_float(orw[4*g+3]) * inv);
                *(float4*)(xrow + hh*32 + 4*g) = ov;
            }
        }
    }

    __syncthreads();
    if (tid == 0) { MBAR_INVAL(sb + SM_SBAR); MBAR_INVAL(sb + SM_PVBAR); }
    __syncthreads();
    if (wid == 0) TCG_DEALLOC(tb, TM_COLS);
#endif  // TCG_OK
}

// ===========================================================================
// Normalize attn rows
// ===========================================================================
__global__ void norm_kernel(float* __restrict__ attn, const float* __restrict__ rinv)
{
    const size_t n4 = (size_t)BB*NH*SS*SS/4;
    for (size_t idx = (size_t)blockIdx.x*blockDim.x + threadIdx.x; idx < n4;
         idx += (size_t)gridDim.x*blockDim.x) {
        float inv = rinv[idx >> 9];
        float4 v = ((const float4*)attn)[idx];
        v.x *= inv; v.y *= inv; v.z *= inv; v.w *= inv;
        ((float4*)attn)[idx] = v;
    }
}

// ===========================================================================
extern "C" void kernel_launch(void* const* d_in, const int* in_sizes, int n_in,
                              void* d_out, int out_size)
{
    const float* query = (const float*)d_in[0];
    const float* key_  = (const float*)d_in[1];
    const float* value = (const float*)d_in[2];
    const unsigned char* mask = (const unsigned char*)d_in[3];
    const int*   pos   = (const int*)d_in[4];
    const float* Wq = (const float*)d_in[5];
    const float* bq = (const float*)d_in[6];
    const float* Wk = (const float*)d_in[7];
    const float* bk = (const float*)d_in[8];
    const float* Wv = (const float*)d_in[9];
    const float* bv = (const float*)d_in[10];
    const float* Wo = (const float*)d_in[11];
    const float* bo = (const float*)d_in[12];
    const float* rel = (const float*)d_in[13];

    float* out  = (float*)d_out;                     // (B,S,HID)
    float* attn = out + (size_t)BSROWS*HID;          // (B,H,S,S)

    float *qb, *kb, *vb, *xb, *crb, *rb;
    __nv_bfloat16 *wth, *wtl;
    cudaGetSymbolAddress((void**)&qb, g_q);
    cudaGetSymbolAddress((void**)&kb, g_k);
    cudaGetSymbolAddress((void**)&vb, g_v);
    cudaGetSymbolAddress((void**)&xb, g_x);
    cudaGetSymbolAddress((void**)&crb, g_cr);
    cudaGetSymbolAddress((void**)&rb, g_rinv);
    cudaGetSymbolAddress((void**)&wth, g_wth);
    cudaGetSymbolAddress((void**)&wtl, g_wtl);

    cudaFuncSetAttribute(attn_tc_kernel,
                         cudaFuncAttributeMaxDynamicSharedMemorySize, SM_TOTAL);
    cudaFuncSetAttribute(gemm_tc_kernel,
                         cudaFuncAttributeMaxDynamicSharedMemorySize, GM_TOTAL);

    // weight transpose+split (all 4 matrices)
    wprep_kernel<<<dim3(16, 16, 4), dim3(32, 8)>>>(Wq, Wk, Wv, Wo, wth, wtl);

    const size_t WSZ = (size_t)HID*HID;
    dim3 ggrid(HID/128, BSROWS/128);   // (4, 32)
    gemm_tc_kernel<<<ggrid, 128, GM_TOTAL>>>(query, wth + 0*WSZ, wtl + 0*WSZ, bq, qb);
    gemm_tc_kernel<<<ggrid, 128, GM_TOTAL>>>(key_,  wth + 1*WSZ, wtl + 1*WSZ, bk, kb);
    gemm_tc_kernel<<<ggrid, 128, GM_TOTAL>>>(value, wth + 2*WSZ, wtl + 2*WSZ, bv, vb);

    cr_kernel<<<(BSROWS*NH*32 + 255)/256, 256>>>(qb, kb, rel, crb);

    attn_tc_kernel<<<dim3(SS/128, BB*NH), 128, SM_TOTAL>>>(
        qb, kb, vb, crb, pos, mask, attn, xb, rb);

    norm_kernel<<<2048, 256>>>(attn, rb);

    gemm_tc_kernel<<<ggrid, 128, GM_TOTAL>>>(xb, wth + 3*WSZ, wtl + 3*WSZ, bo, out);
}

// round 10
// speedup vs baseline: 1.3032x; 1.0279x over previous
#include <cuda_runtime.h>
#include <cuda_bf16.h>
#include <cstdint>
#include <cstddef>

#define BB 2
#define SS 2048
#define HID 512
#define NH 8
#define DH 64
#define BSROWS (BB*SS)   // 4096

// tcgen05 is arch-SPECIFIC: only emit in sm_103a/sm_100a passes, never the
// generic compute_103 pass (ptxas rejects it there — Round-5 failure).
#if defined(__CUDA_ARCH_FEAT_SM103_ALL) || defined(__CUDA_ARCH_FEAT_SM100_ALL) || \
    (defined(__CUDA_ARCH_SPECIFIC__) && (__CUDA_ARCH_SPECIFIC__ >= 1000))
#define TCG_OK 1
#else
#define TCG_OK 0
#endif

// Scratch (device globals — allocation-free rule)
__device__ __align__(16) float g_q[BSROWS*HID];
__device__ __align__(16) float g_k[BSROWS*HID];
__device__ __align__(16) float g_v[BSROWS*HID];
__device__ __align__(16) float g_x[BSROWS*HID];
__device__ __align__(16) float g_cr[BSROWS*NH*4];
__device__ __align__(16) float g_rinv[BB*NH*SS];
__device__ __align__(16) __nv_bfloat16 g_wth[4*HID*HID];  // Wt[n,k] hi
__device__ __align__(16) __nv_bfloat16 g_wtl[4*HID*HID];  // Wt[n,k] lo
__device__ __align__(16) unsigned char g_code[(size_t)BB*SS*SS];  // mask?3:pos

// ===========================================================================
// PTX helpers (arch-specific passes only)
// ===========================================================================
#if TCG_OK
__device__ __forceinline__ uint32_t elect_one_pred() {
    uint32_t pred;
    asm volatile("{\n\t.reg .pred p;\n\telect.sync _|p, 0xFFFFFFFF;\n\t"
                 "selp.b32 %0, 1, 0, p;\n\t}" : "=r"(pred));
    return pred;
}
__device__ __forceinline__ uint32_t smem_u32(const void* p) {
    uint32_t a;
    asm("{ .reg .u64 t; cvta.to.shared.u64 t, %1; cvt.u32.u64 %0, t; }"
        : "=r"(a) : "l"(p));
    return a;
}
#define TCG_ALLOC(sa, n)   asm volatile("tcgen05.alloc.cta_group::1.sync.aligned.shared::cta.b32 [%0], %1;" :: "r"((uint32_t)(sa)), "r"((uint32_t)(n)) : "memory")
#define TCG_DEALLOC(t, n)  asm volatile("tcgen05.dealloc.cta_group::1.sync.aligned.b32 %0, %1;" :: "r"(t), "r"((uint32_t)(n)))
#define TCG_WAIT_LD()      asm volatile("tcgen05.wait::ld.sync.aligned;" ::: "memory")
#define TCG_WAIT_ST()      asm volatile("tcgen05.wait::st.sync.aligned;" ::: "memory")
#define TCG_FENCE_BEFORE() asm volatile("tcgen05.fence::before_thread_sync;" ::: "memory")
#define TCG_FENCE_AFTER()  asm volatile("tcgen05.fence::after_thread_sync;" ::: "memory")
#define TCG_COMMIT(mb)     asm volatile("tcgen05.commit.cta_group::1.mbarrier::arrive::one.shared::cluster.b64 [%0];" :: "r"((uint32_t)(mb)) : "memory")
#define FENCE_ASYNC()      asm volatile("fence.proxy.async.shared::cta;" ::: "memory")
#define MBAR_INIT(mb, c)   asm volatile("mbarrier.init.shared.b64 [%0], %1;" :: "r"((uint32_t)(mb)), "r"((uint32_t)(c)) : "memory")
#define MBAR_INVAL(mb)     asm volatile("mbarrier.inval.shared.b64 [%0];" :: "r"((uint32_t)(mb)) : "memory")

#define MBAR_WAIT(mb, ph) do { \
    uint32_t _m = (uint32_t)(mb), _p = (uint32_t)(ph), _d; \
    asm volatile("{\n\t.reg .pred p;\n\t" \
        "mbarrier.try_wait.parity.acquire.cta.shared::cta.b64 p, [%1], %2;\n\t" \
        "selp.b32 %0, 1, 0, p;\n\t}" : "=r"(_d) : "r"(_m), "r"(_p) : "memory"); \
    if (!_d) { \
        asm volatile("{\n\t.reg .pred P1;\n\t" \
            "WL_%=:\n\t" \
            "mbarrier.try_wait.parity.acquire.cta.shared::cta.b64 P1, [%0], %1, 0x989680;\n\t" \
            "@P1 bra.uni WD_%=;\n\t" \
            "bra.uni WL_%=;\n\t" \
            "WD_%=:\n\t}" :: "r"(_m), "r"(_p) : "memory"); \
    } \
} while (0)

#define TCG_LD_X32(r, ta) \
    asm volatile("tcgen05.ld.sync.aligned.32x32b.x32.b32 " \
        "{%0, %1, %2, %3, %4, %5, %6, %7, %8, %9, %10, %11, %12, %13, %14, %15, " \
        " %16, %17, %18, %19, %20, %21, %22, %23, %24, %25, %26, %27, %28, %29, %30, %31}, [%32];" \
        : "=r"((r)[0]),  "=r"((r)[1]),  "=r"((r)[2]),  "=r"((r)[3]), \
          "=r"((r)[4]),  "=r"((r)[5]),  "=r"((r)[6]),  "=r"((r)[7]), \
          "=r"((r)[8]),  "=r"((r)[9]),  "=r"((r)[10]), "=r"((r)[11]), \
          "=r"((r)[12]), "=r"((r)[13]), "=r"((r)[14]), "=r"((r)[15]), \
          "=r"((r)[16]), "=r"((r)[17]), "=r"((r)[18]), "=r"((r)[19]), \
          "=r"((r)[20]), "=r"((r)[21]), "=r"((r)[22]), "=r"((r)[23]), \
          "=r"((r)[24]), "=r"((r)[25]), "=r"((r)[26]), "=r"((r)[27]), \
          "=r"((r)[28]), "=r"((r)[29]), "=r"((r)[30]), "=r"((r)[31]) \
        : "r"(ta))

#define TCG_ST_X16(ta, r) \
    asm volatile("tcgen05.st.sync.aligned.32x32b.x16.b32 [%0], " \
        "{%1, %2, %3, %4, %5, %6, %7, %8, %9, %10, %11, %12, %13, %14, %15, %16};" \
        :: "r"(ta), \
           "r"((r)[0]),  "r"((r)[1]),  "r"((r)[2]),  "r"((r)[3]), \
           "r"((r)[4]),  "r"((r)[5]),  "r"((r)[6]),  "r"((r)[7]), \
           "r"((r)[8]),  "r"((r)[9]),  "r"((r)[10]), "r"((r)[11]), \
           "r"((r)[12]), "r"((r)[13]), "r"((r)[14]), "r"((r)[15]) \
        : "memory")

__device__ __forceinline__ void mma_f16_ss(uint32_t d_tmem, uint64_t a_desc,
                                           uint64_t b_desc, uint32_t idesc, bool acc) {
    uint32_t en = acc ? 1u : 0u;
    asm volatile("{\n\t.reg .pred p;\n\tsetp.ne.u32 p, %5, 0;\n\t"
        "tcgen05.mma.cta_group::1.kind::f16 [%0], %1, %2, %3, {%4, %4, %4, %4}, p;\n\t}"
        :: "r"(d_tmem), "l"(a_desc), "l"(b_desc), "r"(idesc), "r"(0u), "r"(en) : "memory");
}
__device__ __forceinline__ void mma_f16_ts(uint32_t d_tmem, uint32_t a_tmem,
                                           uint64_t b_desc, uint32_t idesc, bool acc) {
    uint32_t en = acc ? 1u : 0u;
    asm volatile("{\n\t.reg .pred p;\n\tsetp.ne.u32 p, %5, 0;\n\t"
        "tcgen05.mma.cta_group::1.kind::f16 [%0], [%1], %2, %3, {%4, %4, %4, %4}, p;\n\t}"
        :: "r"(d_tmem), "r"(a_tmem), "l"(b_desc), "r"(idesc), "r"(0u), "r"(en) : "memory");
}

static constexpr uint64_t SMEM_DESC_BASE_SW128 =
    (uint64_t(2) << 61) | (uint64_t(1) << 46) | (uint64_t(64) << 32) | (uint64_t(1) << 16);
#define MK_DESC(a) (SMEM_DESC_BASE_SW128 | ((uint64_t)((a) >> 4) & 0x3FFF))
#define SWZ(o) ((o) ^ (((o) >> 3) & 0x70))

__device__ __forceinline__ uint32_t pack_bf16x2(float lo, float hi) {
    uint32_t r; asm("cvt.rn.bf16x2.f32 %0, %1, %2;" : "=r"(r) : "f"(hi), "f"(lo));
    return r;
}

static constexpr uint32_t IDESC_128x64 =
    (1u << 4) | (1u << 7) | (1u << 10) | ((64u/8) << 17) | ((128u/16) << 24);
static constexpr uint32_t IDESC_128x128 =
    (1u << 4) | (1u << 7) | (1u << 10) | ((128u/8) << 17) | ((128u/16) << 24);
#endif  // TCG_OK

// ===========================================================================
// Weight prep: Wt[n,k] (hi/lo bf16) = transpose+split of W[k,n], all 4 mats.
// ===========================================================================
__global__ void wprep_kernel(const float* __restrict__ W0, const float* __restrict__ W1,
                             const float* __restrict__ W2, const float* __restrict__ W3,
                             __nv_bfloat16* __restrict__ wth, __nv_bfloat16* __restrict__ wtl)
{
    __shared__ float tile[32][33];
    const int z = blockIdx.z;
    const float* W = (z == 0) ? W0 : (z == 1) ? W1 : (z == 2) ? W2 : W3;
    const int n0 = blockIdx.x * 32, k0 = blockIdx.y * 32;
    const int tx = threadIdx.x, ty = threadIdx.y;
#pragma unroll
    for (int i = ty; i < 32; i += 8)
        tile[i][tx] = W[(size_t)(k0 + i)*HID + n0 + tx];
    __syncthreads();
#pragma unroll
    for (int i = ty; i < 32; i += 8) {
        float v = tile[tx][i];
        __nv_bfloat16 h = __float2bfloat16(v);
        __nv_bfloat16 l = __float2bfloat16(v - __bfloat162float(h));
        size_t o = (size_t)z*HID*HID + (size_t)(n0 + i)*HID + k0 + tx;
        wth[o] = h; wtl[o] = l;
    }
}

// ===========================================================================
// code prep: code[b,i,j] = mask[b,i,j] ? 3 : (uint8)pos[i,j]
// ===========================================================================
__global__ void code_kernel(const int* __restrict__ pos,
                            const unsigned char* __restrict__ mask,
                            unsigned char* __restrict__ code)
{
    const size_t n4 = (size_t)BB*SS*SS/4;
    const size_t ps4 = (size_t)SS*SS/4;
    for (size_t idx = (size_t)blockIdx.x*blockDim.x + threadIdx.x; idx < n4;
         idx += (size_t)gridDim.x*blockDim.x) {
        size_t prem = idx % ps4;
        int4 pp = *(const int4*)(pos + prem*4);
        uchar4 mm = ((const uchar4*)mask)[idx];
        uchar4 o;
        o.x = mm.x ? 3 : (unsigned char)pp.x;
        o.y = mm.y ? 3 : (unsigned char)pp.y;
        o.z = mm.z ? 3 : (unsigned char)pp.z;
        o.w = mm.w ? 3 : (unsigned char)pp.w;
        ((uchar4*)code)[idx] = o;
    }
}

// ===========================================================================
// tcgen05 GEMM: C[4096,512] = A @ W + bias. 128x128 tile, double-buffered
// with ONE MBARRIER PER STAGE (single-barrier parity deadlocks at lead 2 —
// the Round-8/9 hang). Coalesced loads, staged coalesced epilogue.
// ===========================================================================
#define GM_TPTR   0
#define GM_BAR0   8
#define GM_BAR1   16
#define GM_BUF    1024               // 2 stages x 64KB (AH|AL|BH|BL 16KB each)
#define GM_TOTAL  (1024 + 2*65536)   // 132096

__global__ __launch_bounds__(128) void gemm_tc_kernel(
    const float* __restrict__ A,
    const __nv_bfloat16* __restrict__ Wth, const __nv_bfloat16* __restrict__ Wtl,
    const float* __restrict__ bias, float* __restrict__ C)
{
#if TCG_OK
    extern __shared__ char smem8[];
    const uint32_t sb = smem_u32(smem8);
    const int tid = threadIdx.x;
    const int wid = tid >> 5;
    const int row0 = blockIdx.y * 128, col0 = blockIdx.x * 128;

    if (wid == 0) TCG_ALLOC(sb + GM_TPTR, 128);
    if (tid == 0) { MBAR_INIT(sb + GM_BAR0, 1); MBAR_INIT(sb + GM_BAR1, 1); }
    __syncthreads();
    uint32_t tb;
    asm volatile("ld.shared.b32 %0, [%1];" : "=r"(tb) : "r"(sb + GM_TPTR));

    uint32_t pv0 = 0, pv1 = 0;
    for (int ch = 0; ch < 8; ++ch) {
        const int s = ch & 1;
        char* bufAH = smem8 + GM_BUF + s*65536;
        char* bufAL = bufAH + 16384;
        char* bufBH = bufAH + 32768;
        char* bufBL = bufAH + 49152;
        // Wait for MMA(ch-2) — same stage, producer lead exactly 1 phase.
        if (ch >= 2) {
            if (s == 0) { MBAR_WAIT(sb + GM_BAR0, pv0); pv0 ^= 1; }
            else        { MBAR_WAIT(sb + GM_BAR1, pv1); pv1 ^= 1; }
        }
        __syncthreads();

        // A tile 128x64 f32, COALESCED (lanes -> consecutive cols), split bf16
#pragma unroll
        for (int pss = 0; pss < 16; ++pss) {
            int idx = pss*128 + tid;
            int row = idx >> 4, u = idx & 15;
            float4 a = *(const float4*)(A + (size_t)(row0 + row)*HID + ch*64 + 4*u);
            uint32_t h01 = pack_bf16x2(a.x, a.y);
            uint32_t h23 = pack_bf16x2(a.z, a.w);
            float r0 = a.x - __uint_as_float(h01 << 16);
            float r1 = a.y - __uint_as_float(h01 & 0xffff0000u);
            float r2 = a.z - __uint_as_float(h23 << 16);
            float r3 = a.w - __uint_as_float(h23 & 0xffff0000u);
            uint32_t o = SWZ((uint32_t)(row*128 + u*8));
            *(uint2*)(bufAH + o) = make_uint2(h01, h23);
            *(uint2*)(bufAL + o) = make_uint2(pack_bf16x2(r0, r1), pack_bf16x2(r2, r3));
        }
        // W tiles 128x64 bf16, COALESCED uint4 copies
#pragma unroll
        for (int pss = 0; pss < 8; ++pss) {
            int idx = pss*128 + tid;
            int n = idx >> 3, u = idx & 7;
            uint32_t o = SWZ((uint32_t)(n*128 + u*16));
            *(uint4*)(bufBH + o) =
                *(const uint4*)(Wth + (size_t)(col0 + n)*HID + ch*64 + 8*u);
            *(uint4*)(bufBL + o) =
                *(const uint4*)(Wtl + (size_t)(col0 + n)*HID + ch*64 + 8*u);
        }
        FENCE_ASYNC();
        __syncthreads();

        if (wid == 0) {
            if (elect_one_pred()) {
                uint64_t dAH = MK_DESC(sb + GM_BUF + s*65536);
                uint64_t dAL = dAH + (16384 >> 4);
                uint64_t dBH = dAH + (32768 >> 4);
                uint64_t dBL = dAH + (49152 >> 4);
#pragma unroll
                for (int m = 0; m < 3; ++m) {
                    uint64_t ad = (m == 2) ? dAL : dAH;
                    uint64_t bd = (m == 1) ? dBL : dBH;
#pragma unroll
                    for (int ks = 0; ks < 4; ++ks)
                        mma_f16_ss(tb, ad + ks*2, bd + ks*2, IDESC_128x128,
                                   !(ch == 0 && m == 0 && ks == 0));
                }
                TCG_COMMIT(sb + ((s == 0) ? GM_BAR0 : GM_BAR1));
            }
        }
    }
    // Drain: commits 6 (bar0, parity pv0) and 7 (bar1, parity pv1).
    MBAR_WAIT(sb + GM_BAR0, pv0);
    MBAR_WAIT(sb + GM_BAR1, pv1);
    TCG_FENCE_AFTER();

    // staged coalesced epilogue: 4 quarters of 32 cols
    {
        float* stg = (float*)(smem8 + GM_BUF);   // buffers are free now
#pragma unroll
        for (int hh = 0; hh < 4; ++hh) {
            uint32_t dr[32];
            TCG_LD_X32(dr, tb + hh*32);
            TCG_WAIT_LD();
#pragma unroll
            for (int g = 0; g < 8; ++g) {
                float4 bv = *(const float4*)(bias + col0 + hh*32 + 4*g);
                float4 o = make_float4(__uint_as_float(dr[4*g+0]) + bv.x,
                                       __uint_as_float(dr[4*g+1]) + bv.y,
                                       __uint_as_float(dr[4*g+2]) + bv.z,
                                       __uint_as_float(dr[4*g+3]) + bv.w);
                *(float4*)(stg + tid*36 + 4*g) = o;
            }
            __syncthreads();
#pragma unroll
            for (int it = 0; it < 8; ++it) {
                int idx = it*128 + tid;
                int row = idx >> 3, c = idx & 7;
                float4 vv = *(float4*)(stg + row*36 + 4*c);
                *(float4*)(C + (size_t)(row0 + row)*HID + col0 + hh*32 + 4*c) = vv;
            }
            __syncthreads();
        }
    }

    if (tid == 0) { MBAR_INVAL(sb + GM_BAR0); MBAR_INVAL(sb + GM_BAR1); }
    __syncthreads();
    if (wid == 0) TCG_DEALLOC(tb, 128);
#endif  // TCG_OK
}

// ===========================================================================
// cr_kernel (unchanged)
// ===========================================================================
__global__ void cr_kernel(const float* __restrict__ q, const float* __restrict__ k,
                          const float* __restrict__ rel, float* __restrict__ cr)
{
    int gw = (int)((blockIdx.x * blockDim.x + threadIdx.x) >> 5);
    int lane = threadIdx.x & 31;
    if (gw >= BSROWS*NH) return;
    int row = gw >> 3, h = gw & 7;
    const float* qp = q + (size_t)row*HID + h*DH;
    const float* kp = k + (size_t)row*HID + h*DH;
    float2 qv = *(const float2*)(qp + lane*2);
    float2 kv = *(const float2*)(kp + lane*2);
    float a0 = qv.x + kv.x, a1 = qv.y + kv.y;
#pragma unroll
    for (int r = 0; r < 3; ++r) {
        float2 rv = *(const float2*)(rel + r*DH + lane*2);
        float s = a0*rv.x + a1*rv.y;
        s += __shfl_xor_sync(0xffffffffu, s, 16);
        s += __shfl_xor_sync(0xffffffffu, s, 8);
        s += __shfl_xor_sync(0xffffffffu, s, 4);
        s += __shfl_xor_sync(0xffffffffu, s, 2);
        s += __shfl_xor_sync(0xffffffffu, s, 1);
        if (lane == 0) cr[(size_t)gw*4 + r] = s;
    }
    if (lane == 0) cr[(size_t)gw*4 + 3] = 0.f;
}

// ===========================================================================
// tcgen05 attention. code-fused bias, staged coalesced attn writes.
// (mbarrier usage here is strictly alternating commit/wait — lead 1, safe,
//  and this pattern passed in Rounds 6-7.)
// ===========================================================================
#define SM_TPTR   0
#define SM_SBAR   8
#define SM_PVBAR  16
#define SM_QH     1024
#define SM_QL     17408
#define SM_KH     33792
#define SM_KL     41984
#define SM_VTH    50176
#define SM_VTL    58368
#define SM_STAGE  66560          // 128 x 36 f32 = 18432B
#define SM_TOTAL  84992

#define TM_S   0
#define TM_O   64
#define TM_PH  128
#define TM_PL  160
#define TM_COLS 256

__global__ __launch_bounds__(128) void attn_tc_kernel(
    const float* __restrict__ q, const float* __restrict__ k,
    const float* __restrict__ v, const float* __restrict__ cr,
    const unsigned char* __restrict__ code,
    float* __restrict__ attn, float* __restrict__ x, float* __restrict__ rinv)
{
#if TCG_OK
    extern __shared__ char smem8[];
    const uint32_t sb = smem_u32(smem8);
    const int tid = threadIdx.x;
    const int wid = tid >> 5;
    const int bh = blockIdx.y, b = bh >> 3, h = bh & 7;
    const int i0 = blockIdx.x * 128;
    const int gi = i0 + tid;
    const uint32_t woff = ((uint32_t)wid) << 21;

    if (wid == 0) TCG_ALLOC(sb + SM_TPTR, TM_COLS);
    if (tid == 0) { MBAR_INIT(sb + SM_SBAR, 1); MBAR_INIT(sb + SM_PVBAR, 1); }
    __syncthreads();
    uint32_t tb;
    asm volatile("ld.shared.b32 %0, [%1];" : "=r"(tb) : "r"(sb + SM_TPTR));

    {   // Q tile (128 x 64) -> split bf16, SW128, coalesced
#pragma unroll
        for (int pss = 0; pss < 16; ++pss) {
            int idx = pss*128 + tid;
            int row = idx >> 4, u = idx & 15;
            float4 a = *(const float4*)(q + (size_t)(b*SS + i0 + row)*HID + h*DH + 4*u);
            uint32_t h01 = pack_bf16x2(a.x, a.y);
            uint32_t h23 = pack_bf16x2(a.z, a.w);
            float r0 = a.x - __uint_as_float(h01 << 16);
            float r1 = a.y - __uint_as_float(h01 & 0xffff0000u);
            float r2 = a.z - __uint_as_float(h23 << 16);
            float r3 = a.w - __uint_as_float(h23 & 0xffff0000u);
            uint32_t o = SWZ((uint32_t)(row*128 + u*8));
            *(uint2*)(smem8 + SM_QH + o) = make_uint2(h01, h23);
            *(uint2*)(smem8 + SM_QL + o) = make_uint2(pack_bf16x2(r0, r1), pack_bf16x2(r2, r3));
        }
    }
    float c0, c1, c2;
    {
        const float* cp = cr + (size_t)((b*SS + gi)*NH + h)*4;
        c0 = cp[0]; c1 = cp[1]; c2 = cp[2];
    }
    FENCE_ASYNC();

    const uint64_t dQH = MK_DESC(sb + SM_QH), dQL = MK_DESC(sb + SM_QL);
    const uint64_t dKH = MK_DESC(sb + SM_KH), dKL = MK_DESC(sb + SM_KL);
    const uint64_t dVH = MK_DESC(sb + SM_VTH), dVL = MK_DESC(sb + SM_VTL);
    float* stg = (float*)(smem8 + SM_STAGE);

    float rsum = 0.f;
    uint32_t sp = 0, pvp = 0;

    for (int t = 0, j0 = 0; j0 < SS; ++t, j0 += 64) {
        if (t > 0) { MBAR_WAIT(sb + SM_PVBAR, pvp); pvp ^= 1; }
        __syncthreads();

        {   // K (64x64) split bf16 + V transposed
            int r = tid >> 1;
            int dc = (tid & 1) * 32;
            const float* krow = k + (size_t)(b*SS + j0 + r)*HID + h*DH + dc;
            const float* vrow = v + (size_t)(b*SS + j0 + r)*HID + h*DH + dc;
#pragma unroll
            for (int u = 0; u < 8; ++u) {
                int d0 = dc + 4*u;
                float4 a = *(const float4*)(krow + 4*u);
                uint32_t h01 = pack_bf16x2(a.x, a.y);
                uint32_t h23 = pack_bf16x2(a.z, a.w);
                float r0 = a.x - __uint_as_float(h01 << 16);
                float r1 = a.y - __uint_as_float(h01 & 0xffff0000u);
                float r2 = a.z - __uint_as_float(h23 << 16);
                float r3 = a.w - __uint_as_float(h23 & 0xffff0000u);
                uint32_t o = SWZ((uint32_t)(r*128 + d0*2));
                *(uint2*)(smem8 + SM_KH + o) = make_uint2(h01, h23);
                *(uint2*)(smem8 + SM_KL + o) =
                    make_uint2(pack_bf16x2(r0, r1), pack_bf16x2(r2, r3));

                float4 vv = *(const float4*)(vrow + 4*u);
                float ve[4] = {vv.x, vv.y, vv.z, vv.w};
#pragma unroll
                for (int e = 0; e < 4; ++e) {
                    int d = d0 + e;
                    __nv_bfloat16 vh = __float2bfloat16(ve[e]);
                    __nv_bfloat16 vl = __float2bfloat16(ve[e] - __bfloat162float(vh));
                    uint32_t ov = SWZ((uint32_t)(d*128 + r*2));
                    *(__nv_bfloat16*)(smem8 + SM_VTH + ov) = vh;
                    *(__nv_bfloat16*)(smem8 + SM_VTL + ov) = vl;
                }
            }
        }
        FENCE_ASYNC();
        __syncthreads();

        // S = QhKh + QhKl + QlKh
        if (wid == 0) {
            if (elect_one_pred()) {
#pragma unroll
                for (int m = 0; m < 3; ++m) {
                    uint64_t ad = (m == 2) ? dQL : dQH;
                    uint64_t bd = (m == 1) ? dKL : dKH;
#pragma unroll
                    for (int ks = 0; ks < 4; ++ks)
                        mma_f16_ss(tb + TM_S, ad + ks*2, bd + ks*2, IDESC_128x64,
                                   !(m == 0 && ks == 0));
                }
                TCG_COMMIT(sb + SM_SBAR);
            }
        }
        MBAR_WAIT(sb + SM_SBAR, sp); sp ^= 1;
        TCG_FENCE_AFTER();

        // epilogue: two halves of 32 cols
#pragma unroll
        for (int hh = 0; hh < 2; ++hh) {
            uint32_t sr[32];
            TCG_LD_X32(sr, tb + TM_S + hh*32);
            TCG_WAIT_LD();
            float p[32];
            const int jc0 = j0 + hh*32;
            // fused pos/mask codes: 32 bytes for this thread's row
            uint32_t cw[8];
            {
                const uint32_t* crow2 =
                    (const uint32_t*)(code + (size_t)b*SS*SS + (size_t)gi*SS + jc0);
                uint4 w0 = *(const uint4*)crow2;
                uint4 w1 = *(const uint4*)(crow2 + 4);
                cw[0]=w0.x; cw[1]=w0.y; cw[2]=w0.z; cw[3]=w0.w;
                cw[4]=w1.x; cw[5]=w1.y; cw[6]=w1.z; cw[7]=w1.w;
            }
#pragma unroll
            for (int g = 0; g < 8; ++g) {
#pragma unroll
                for (int e = 0; e < 4; ++e) {
                    uint32_t cd = (cw[g] >> (8*e)) & 0xFFu;
                    float bias = (cd == 0) ? c0 : ((cd == 1) ? c1 :
                                 ((cd == 2) ? c2 : -3.0e10f));
                    float s = (__uint_as_float(sr[4*g + e]) + bias) * 0.125f;
                    float pe = __expf(s);      // masked -> exp(-3.75e9) = 0
                    p[4*g + e] = pe;
                    rsum += pe;
                }
            }
            // stage P -> coalesced attn write
#pragma unroll
            for (int c = 0; c < 8; ++c)
                *(float4*)(stg + tid*36 + 4*c) =
                    make_float4(p[4*c], p[4*c+1], p[4*c+2], p[4*c+3]);
            __syncthreads();
            {
                float* abase = attn + ((size_t)bh*SS + i0)*SS + jc0;
#pragma unroll
                for (int it = 0; it < 8; ++it) {
                    int idx = it*128 + tid;
                    int row = idx >> 3, c = idx & 7;
                    float4 vv = *(float4*)(stg + row*36 + 4*c);
                    *(float4*)(abase + (size_t)row*SS + 4*c) = vv;
                }
            }
            __syncthreads();
            // pack P hi/lo -> TMEM
            uint32_t ph[16], pl[16];
#pragma unroll
            for (int c = 0; c < 16; ++c) {
                float p0 = p[2*c], p1 = p[2*c+1];
                uint32_t hp = pack_bf16x2(p0, p1);
                ph[c] = hp;
                pl[c] = pack_bf16x2(p0 - __uint_as_float(hp << 16),
                                    p1 - __uint_as_float(hp & 0xffff0000u));
            }
            TCG_ST_X16(tb + TM_PH + hh*16 + woff, ph);
            TCG_ST_X16(tb + TM_PL + hh*16 + woff, pl);
            TCG_WAIT_ST();
        }
        TCG_FENCE_BEFORE();
        __syncthreads();

        // O += PhVh + PhVl + PlVh
        if (wid == 0) {
            if (elect_one_pred()) {
                TCG_FENCE_AFTER();
#pragma unroll
                for (int m = 0; m < 3; ++m) {
                    uint32_t at = tb + ((m == 2) ? TM_PL : TM_PH);
                    uint64_t bd = (m == 1) ? dVL : dVH;
#pragma unroll
                    for (int ks = 0; ks < 4; ++ks)
                        mma_f16_ts(tb + TM_O, at + ks*8, bd + ks*2, IDESC_128x64,
                                   !(t == 0 && m == 0 && ks == 0));
                }
                TCG_COMMIT(sb + SM_PVBAR);
            }
        }
    }

    MBAR_WAIT(sb + SM_PVBAR, pvp);
    TCG_FENCE_AFTER();

    {
        float inv = 1.0f / rsum;
        rinv[(size_t)bh*SS + gi] = inv;
        float* xrow = x + (size_t)(b*SS + gi)*HID + h*DH;
#pragma unroll
        for (int hh = 0; hh < 2; ++hh) {
            uint32_t orw[32];
            TCG_LD_X32(orw, tb + TM_O + hh*32);
            TCG_WAIT_LD();
#pragma unroll
            for (int g = 0; g < 8; ++g) {
                float4 ov = make_float4(__uint_as_float(orw[4*g+0]) * inv,
                                        __uint_as_float(orw[4*g+1]) * inv,
                                        __uint_as_float(orw[4*g+2]) * inv,
                                        __uint_as_float(orw[4*g+3]) * inv);
                *(float4*)(xrow + hh*32 + 4*g) = ov;
            }
        }
    }

    __syncthreads();
    if (tid == 0) { MBAR_INVAL(sb + SM_SBAR); MBAR_INVAL(sb + SM_PVBAR); }
    __syncthreads();
    if (wid == 0) TCG_DEALLOC(tb, TM_COLS);
#endif  // TCG_OK
}

// ===========================================================================
// Normalize attn rows
// ===========================================================================
__global__ void norm_kernel(float* __restrict__ attn, const float* __restrict__ rinv)
{
    const size_t n4 = (size_t)BB*NH*SS*SS/4;
    for (size_t idx = (size_t)blockIdx.x*blockDim.x + threadIdx.x; idx < n4;
         idx += (size_t)gridDim.x*blockDim.x) {
        float inv = rinv[idx >> 9];
        float4 v = ((const float4*)attn)[idx];
        v.x *= inv; v.y *= inv; v.z *= inv; v.w *= inv;
        ((float4*)attn)[idx] = v;
    }
}

// ===========================================================================
extern "C" void kernel_launch(void* const* d_in, const int* in_sizes, int n_in,
                              void* d_out, int out_size)
{
    const float* query = (const float*)d_in[0];
    const float* key_  = (const float*)d_in[1];
    const float* value = (const float*)d_in[2];
    const unsigned char* mask = (const unsigned char*)d_in[3];
    const int*   pos   = (const int*)d_in[4];
    const float* Wq = (const float*)d_in[5];
    const float* bq = (const float*)d_in[6];
    const float* Wk = (const float*)d_in[7];
    const float* bk = (const float*)d_in[8];
    const float* Wv = (const float*)d_in[9];
    const float* bv = (const float*)d_in[10];
    const float* Wo = (const float*)d_in[11];
    const float* bo = (const float*)d_in[12];
    const float* rel = (const float*)d_in[13];

    float* out  = (float*)d_out;                     // (B,S,HID)
    float* attn = out + (size_t)BSROWS*HID;          // (B,H,S,S)

    float *qb, *kb, *vb, *xb, *crb, *rb;
    __nv_bfloat16 *wth, *wtl;
    unsigned char* codeb;
    cudaGetSymbolAddress((void**)&qb, g_q);
    cudaGetSymbolAddress((void**)&kb, g_k);
    cudaGetSymbolAddress((void**)&vb, g_v);
    cudaGetSymbolAddress((void**)&xb, g_x);
    cudaGetSymbolAddress((void**)&crb, g_cr);
    cudaGetSymbolAddress((void**)&rb, g_rinv);
    cudaGetSymbolAddress((void**)&wth, g_wth);
    cudaGetSymbolAddress((void**)&wtl, g_wtl);
    cudaGetSymbolAddress((void**)&codeb, g_code);

    cudaFuncSetAttribute(attn_tc_kernel,
                         cudaFuncAttributeMaxDynamicSharedMemorySize, SM_TOTAL);
    cudaFuncSetAttribute(gemm_tc_kernel,
                         cudaFuncAttributeMaxDynamicSharedMemorySize, GM_TOTAL);

    wprep_kernel<<<dim3(16, 16, 4), dim3(32, 8)>>>(Wq, Wk, Wv, Wo, wth, wtl);
    code_kernel<<<2048, 256>>>(pos, mask, codeb);

    const size_t WSZ = (size_t)HID*HID;
    dim3 ggrid(HID/128, BSROWS/128);   // (4, 32)
    gemm_tc_kernel<<<ggrid, 128, GM_TOTAL>>>(query, wth + 0*WSZ, wtl + 0*WSZ, bq, qb);
    gemm_tc_kernel<<<ggrid, 128, GM_TOTAL>>>(key_,  wth + 1*WSZ, wtl + 1*WSZ, bk, kb);
    gemm_tc_kernel<<<ggrid, 128, GM_TOTAL>>>(value, wth + 2*WSZ, wtl + 2*WSZ, bv, vb);

    cr_kernel<<<(BSROWS*NH*32 + 255)/256, 256>>>(qb, kb, rel, crb);

    attn_tc_kernel<<<dim3(SS/128, BB*NH), 128, SM_TOTAL>>>(
        qb, kb, vb, crb, codeb, attn, xb, rb);

    norm_kernel<<<2048, 256>>>(attn, rb);

    gemm_tc_kernel<<<ggrid, 128, GM_TOTAL>>>(xb, wth + 3*WSZ, wtl + 3*WSZ, bo, out);
}

// round 12
// speedup vs baseline: 1.4122x; 1.0837x over previous
#include <cuda_runtime.h>
#include <cuda_bf16.h>
#include <cstdint>
#include <cstddef>

#define BB 2
#define SS 2048
#define HID 512
#define NH 8
#define DH 64
#define BSROWS (BB*SS)   // 4096

// tcgen05 is arch-SPECIFIC: only emit in sm_103a/sm_100a passes, never the
// generic compute_103 pass (ptxas rejects it there — Round-5 failure).
#if defined(__CUDA_ARCH_FEAT_SM103_ALL) || defined(__CUDA_ARCH_FEAT_SM100_ALL) || \
    (defined(__CUDA_ARCH_SPECIFIC__) && (__CUDA_ARCH_SPECIFIC__ >= 1000))
#define TCG_OK 1
#else
#define TCG_OK 0
#endif

// Scratch (device globals — allocation-free rule)
__device__ __align__(16) float g_q[BSROWS*HID];
__device__ __align__(16) float g_k[BSROWS*HID];
__device__ __align__(16) float g_v[BSROWS*HID];
__device__ __align__(16) float g_x[BSROWS*HID];
__device__ __align__(16) float g_cr[BSROWS*NH*4];
__device__ __align__(16) float g_rinv[BB*NH*SS];
__device__ __align__(16) __nv_bfloat16 g_wth[4*HID*HID];  // Wt[n,k] hi
__device__ __align__(16) __nv_bfloat16 g_wtl[4*HID*HID];  // Wt[n,k] lo
__device__ __align__(16) unsigned char g_code[(size_t)BB*SS*SS];  // mask?3:pos

// ===========================================================================
// PTX helpers (arch-specific passes only)
// ===========================================================================
#if TCG_OK
__device__ __forceinline__ uint32_t elect_one_pred() {
    uint32_t pred;
    asm volatile("{\n\t.reg .pred p;\n\telect.sync _|p, 0xFFFFFFFF;\n\t"
                 "selp.b32 %0, 1, 0, p;\n\t}" : "=r"(pred));
    return pred;
}
__device__ __forceinline__ uint32_t smem_u32(const void* p) {
    uint32_t a;
    asm("{ .reg .u64 t; cvta.to.shared.u64 t, %1; cvt.u32.u64 %0, t; }"
        : "=r"(a) : "l"(p));
    return a;
}
#define TCG_ALLOC(sa, n)   asm volatile("tcgen05.alloc.cta_group::1.sync.aligned.shared::cta.b32 [%0], %1;" :: "r"((uint32_t)(sa)), "r"((uint32_t)(n)) : "memory")
#define TCG_DEALLOC(t, n)  asm volatile("tcgen05.dealloc.cta_group::1.sync.aligned.b32 %0, %1;" :: "r"(t), "r"((uint32_t)(n)))
#define TCG_WAIT_LD()      asm volatile("tcgen05.wait::ld.sync.aligned;" ::: "memory")
#define TCG_WAIT_ST()      asm volatile("tcgen05.wait::st.sync.aligned;" ::: "memory")
#define TCG_FENCE_BEFORE() asm volatile("tcgen05.fence::before_thread_sync;" ::: "memory")
#define TCG_FENCE_AFTER()  asm volatile("tcgen05.fence::after_thread_sync;" ::: "memory")
#define TCG_COMMIT(mb)     asm volatile("tcgen05.commit.cta_group::1.mbarrier::arrive::one.shared::cluster.b64 [%0];" :: "r"((uint32_t)(mb)) : "memory")
#define FENCE_ASYNC()      asm volatile("fence.proxy.async.shared::cta;" ::: "memory")
#define MBAR_INIT(mb, c)   asm volatile("mbarrier.init.shared.b64 [%0], %1;" :: "r"((uint32_t)(mb)), "r"((uint32_t)(c)) : "memory")
#define MBAR_INVAL(mb)     asm volatile("mbarrier.inval.shared.b64 [%0];" :: "r"((uint32_t)(mb)) : "memory")

#define MBAR_WAIT(mb, ph) do { \
    uint32_t _m = (uint32_t)(mb), _p = (uint32_t)(ph), _d; \
    asm volatile("{\n\t.reg .pred p;\n\t" \
        "mbarrier.try_wait.parity.acquire.cta.shared::cta.b64 p, [%1], %2;\n\t" \
        "selp.b32 %0, 1, 0, p;\n\t}" : "=r"(_d) : "r"(_m), "r"(_p) : "memory"); \
    if (!_d) { \
        asm volatile("{\n\t.reg .pred P1;\n\t" \
            "WL_%=:\n\t" \
            "mbarrier.try_wait.parity.acquire.cta.shared::cta.b64 P1, [%0], %1, 0x989680;\n\t" \
            "@P1 bra.uni WD_%=;\n\t" \
            "bra.uni WL_%=;\n\t" \
            "WD_%=:\n\t}" :: "r"(_m), "r"(_p) : "memory"); \
    } \
} while (0)

#define TCG_LD_X32(r, ta) \
    asm volatile("tcgen05.ld.sync.aligned.32x32b.x32.b32 " \
        "{%0, %1, %2, %3, %4, %5, %6, %7, %8, %9, %10, %11, %12, %13, %14, %15, " \
        " %16, %17, %18, %19, %20, %21, %22, %23, %24, %25, %26, %27, %28, %29, %30, %31}, [%32];" \
        : "=r"((r)[0]),  "=r"((r)[1]),  "=r"((r)[2]),  "=r"((r)[3]), \
          "=r"((r)[4]),  "=r"((r)[5]),  "=r"((r)[6]),  "=r"((r)[7]), \
          "=r"((r)[8]),  "=r"((r)[9]),  "=r"((r)[10]), "=r"((r)[11]), \
          "=r"((r)[12]), "=r"((r)[13]), "=r"((r)[14]), "=r"((r)[15]), \
          "=r"((r)[16]), "=r"((r)[17]), "=r"((r)[18]), "=r"((r)[19]), \
          "=r"((r)[20]), "=r"((r)[21]), "=r"((r)[22]), "=r"((r)[23]), \
          "=r"((r)[24]), "=r"((r)[25]), "=r"((r)[26]), "=r"((r)[27]), \
          "=r"((r)[28]), "=r"((r)[29]), "=r"((r)[30]), "=r"((r)[31]) \
        : "r"(ta))

#define TCG_ST_X16(ta, r) \
    asm volatile("tcgen05.st.sync.aligned.32x32b.x16.b32 [%0], " \
        "{%1, %2, %3, %4, %5, %6, %7, %8, %9, %10, %11, %12, %13, %14, %15, %16};" \
        :: "r"(ta), \
           "r"((r)[0]),  "r"((r)[1]),  "r"((r)[2]),  "r"((r)[3]), \
           "r"((r)[4]),  "r"((r)[5]),  "r"((r)[6]),  "r"((r)[7]), \
           "r"((r)[8]),  "r"((r)[9]),  "r"((r)[10]), "r"((r)[11]), \
           "r"((r)[12]), "r"((r)[13]), "r"((r)[14]), "r"((r)[15]) \
        : "memory")

__device__ __forceinline__ void mma_f16_ss(uint32_t d_tmem, uint64_t a_desc,
                                           uint64_t b_desc, uint32_t idesc, bool acc) {
    uint32_t en = acc ? 1u : 0u;
    asm volatile("{\n\t.reg .pred p;\n\tsetp.ne.u32 p, %5, 0;\n\t"
        "tcgen05.mma.cta_group::1.kind::f16 [%0], %1, %2, %3, {%4, %4, %4, %4}, p;\n\t}"
        :: "r"(d_tmem), "l"(a_desc), "l"(b_desc), "r"(idesc), "r"(0u), "r"(en) : "memory");
}
__device__ __forceinline__ void mma_f16_ts(uint32_t d_tmem, uint32_t a_tmem,
                                           uint64_t b_desc, uint32_t idesc, bool acc) {
    uint32_t en = acc ? 1u : 0u;
    asm volatile("{\n\t.reg .pred p;\n\tsetp.ne.u32 p, %5, 0;\n\t"
        "tcgen05.mma.cta_group::1.kind::f16 [%0], [%1], %2, %3, {%4, %4, %4, %4}, p;\n\t}"
        :: "r"(d_tmem), "r"(a_tmem), "l"(b_desc), "r"(idesc), "r"(0u), "r"(en) : "memory");
}

static constexpr uint64_t SMEM_DESC_BASE_SW128 =
    (uint64_t(2) << 61) | (uint64_t(1) << 46) | (uint64_t(64) << 32) | (uint64_t(1) << 16);
#define MK_DESC(a) (SMEM_DESC_BASE_SW128 | ((uint64_t)((a) >> 4) & 0x3FFF))
#define SWZ(o) ((o) ^ (((o) >> 3) & 0x70))

__device__ __forceinline__ uint32_t pack_bf16x2(float lo, float hi) {
    uint32_t r; asm("cvt.rn.bf16x2.f32 %0, %1, %2;" : "=r"(r) : "f"(hi), "f"(lo));
    return r;
}

static constexpr uint32_t IDESC_128x64 =
    (1u << 4) | (1u << 7) | (1u << 10) | ((64u/8) << 17) | ((128u/16) << 24);
static constexpr uint32_t IDESC_128x128 =
    (1u << 4) | (1u << 7) | (1u << 10) | ((128u/8) << 17) | ((128u/16) << 24);
#endif  // TCG_OK

// ===========================================================================
// Weight prep: Wt[n,k] (hi/lo bf16) = transpose+split of W[k,n], all 4 mats.
// ===========================================================================
__global__ void wprep_kernel(const float* __restrict__ W0, const float* __restrict__ W1,
                             const float* __restrict__ W2, const float* __restrict__ W3,
                             __nv_bfloat16* __restrict__ wth, __nv_bfloat16* __restrict__ wtl)
{
    __shared__ float tile[32][33];
    const int z = blockIdx.z;
    const float* W = (z == 0) ? W0 : (z == 1) ? W1 : (z == 2) ? W2 : W3;
    const int n0 = blockIdx.x * 32, k0 = blockIdx.y * 32;
    const int tx = threadIdx.x, ty = threadIdx.y;
#pragma unroll
    for (int i = ty; i < 32; i += 8)
        tile[i][tx] = W[(size_t)(k0 + i)*HID + n0 + tx];
    __syncthreads();
#pragma unroll
    for (int i = ty; i < 32; i += 8) {
        float v = tile[tx][i];
        __nv_bfloat16 h = __float2bfloat16(v);
        __nv_bfloat16 l = __float2bfloat16(v - __bfloat162float(h));
        size_t o = (size_t)z*HID*HID + (size_t)(n0 + i)*HID + k0 + tx;
        wth[o] = h; wtl[o] = l;
    }
}

// ===========================================================================
// code prep: code[b,i,j] = mask[b,i,j] ? 3 : (uint8)pos[i,j]
// ===========================================================================
__global__ void code_kernel(const int* __restrict__ pos,
                            const unsigned char* __restrict__ mask,
                            unsigned char* __restrict__ code)
{
    const size_t n4 = (size_t)BB*SS*SS/4;
    const size_t ps4 = (size_t)SS*SS/4;
    for (size_t idx = (size_t)blockIdx.x*blockDim.x + threadIdx.x; idx < n4;
         idx += (size_t)gridDim.x*blockDim.x) {
        size_t prem = idx % ps4;
        int4 pp = *(const int4*)(pos + prem*4);
        uchar4 mm = ((const uchar4*)mask)[idx];
        uchar4 o;
        o.x = mm.x ? 3 : (unsigned char)pp.x;
        o.y = mm.y ? 3 : (unsigned char)pp.y;
        o.z = mm.z ? 3 : (unsigned char)pp.z;
        o.w = mm.w ? 3 : (unsigned char)pp.w;
        ((uchar4*)code)[idx] = o;
    }
}

// ===========================================================================
// tcgen05 GEMM, BATCHED over blockIdx.z (up to 3 A/bias/C triples).
// 128x128 tile, per-stage mbarriers (lead-1, parity-safe), coalesced loads,
// DIRECT per-thread epilogue (staged version was slower — R10 post-mortem).
// ===========================================================================
#define GM_TPTR   0
#define GM_BAR0   8
#define GM_BAR1   16
#define GM_BUF    1024               // 2 stages x 64KB (AH|AL|BH|BL 16KB each)
#define GM_TOTAL  (1024 + 2*65536)   // 132096

__global__ __launch_bounds__(128) void gemm_tc_kernel(
    const float* __restrict__ A0, const float* __restrict__ A1, const float* __restrict__ A2,
    const __nv_bfloat16* __restrict__ WthB, const __nv_bfloat16* __restrict__ WtlB,
    const float* __restrict__ b0, const float* __restrict__ b1, const float* __restrict__ b2,
    float* __restrict__ C0, float* __restrict__ C1, float* __restrict__ C2)
{
#if TCG_OK
    extern __shared__ char smem8[];
    const uint32_t sb = smem_u32(smem8);
    const int tid = threadIdx.x;
    const int wid = tid >> 5;
    const int z = blockIdx.z;
    const float* A    = (z == 0) ? A0 : (z == 1) ? A1 : A2;
    const float* bias = (z == 0) ? b0 : (z == 1) ? b1 : b2;
    float*       C    = (z == 0) ? C0 : (z == 1) ? C1 : C2;
    const __nv_bfloat16* Wth = WthB + (size_t)z*HID*HID;
    const __nv_bfloat16* Wtl = WtlB + (size_t)z*HID*HID;
    const int row0 = blockIdx.y * 128, col0 = blockIdx.x * 128;

    if (wid == 0) TCG_ALLOC(sb + GM_TPTR, 128);
    if (tid == 0) { MBAR_INIT(sb + GM_BAR0, 1); MBAR_INIT(sb + GM_BAR1, 1); }
    __syncthreads();
    uint32_t tb;
    asm volatile("ld.shared.b32 %0, [%1];" : "=r"(tb) : "r"(sb + GM_TPTR));

    uint32_t pv0 = 0, pv1 = 0;
    for (int ch = 0; ch < 8; ++ch) {
        const int s = ch & 1;
        char* bufAH = smem8 + GM_BUF + s*65536;
        char* bufAL = bufAH + 16384;
        char* bufBH = bufAH + 32768;
        char* bufBL = bufAH + 49152;
        // Prefetch globals into registers BEFORE the stage wait (hides L2 lat)
        float4 ar[4];
        uint4  br[2], blr[2];
#pragma unroll
        for (int pss = 0; pss < 4; ++pss) {
            int idx = pss*128 + tid;                 // A: 4 passes of 128
            int row = idx >> 4, u = idx & 15;        // only pass rows 0..31 here
            ar[pss] = *(const float4*)(A + (size_t)(row0 + ((pss*128+tid) >> 4))*HID
                                        + ch*64 + 4*((pss*128+tid) & 15));
            (void)row; (void)u;
        }
#pragma unroll
        for (int pss = 0; pss < 2; ++pss) {
            int idx = pss*128 + tid;
            int n = idx >> 3, u = idx & 7;
            br[pss]  = *(const uint4*)(Wth + (size_t)(col0 + n)*HID + ch*64 + 8*u);
            blr[pss] = *(const uint4*)(Wtl + (size_t)(col0 + n)*HID + ch*64 + 8*u);
        }
        if (ch >= 2) {
            if (s == 0) { MBAR_WAIT(sb + GM_BAR0, pv0); pv0 ^= 1; }
            else        { MBAR_WAIT(sb + GM_BAR1, pv1); pv1 ^= 1; }
        }
        __syncthreads();

        // A tile 128x64 f32 -> split bf16 (first 4 of 16 passes from prefetch)
#pragma unroll
        for (int pss = 0; pss < 16; ++pss) {
            int idx = pss*128 + tid;
            int row = idx >> 4, u = idx & 15;
            float4 a = (pss < 4) ? ar[pss]
                     : *(const float4*)(A + (size_t)(row0 + row)*HID + ch*64 + 4*u);
            uint32_t h01 = pack_bf16x2(a.x, a.y);
            uint32_t h23 = pack_bf16x2(a.z, a.w);
            float r0 = a.x - __uint_as_float(h01 << 16);
            float r1 = a.y - __uint_as_float(h01 & 0xffff0000u);
            float r2 = a.z - __uint_as_float(h23 << 16);
            float r3 = a.w - __uint_as_float(h23 & 0xffff0000u);
            uint32_t o = SWZ((uint32_t)(row*128 + u*8));
            *(uint2*)(bufAH + o) = make_uint2(h01, h23);
            *(uint2*)(bufAL + o) = make_uint2(pack_bf16x2(r0, r1), pack_bf16x2(r2, r3));
        }
        // W tiles (first 2 of 8 passes from prefetch)
#pragma unroll
        for (int pss = 0; pss < 8; ++pss) {
            int idx = pss*128 + tid;
            int n = idx >> 3, u = idx & 7;
            uint32_t o = SWZ((uint32_t)(n*128 + u*16));
            uint4 vh = (pss < 2) ? br[pss]
                     : *(const uint4*)(Wth + (size_t)(col0 + n)*HID + ch*64 + 8*u);
            uint4 vl = (pss < 2) ? blr[pss]
                     : *(const uint4*)(Wtl + (size_t)(col0 + n)*HID + ch*64 + 8*u);
            *(uint4*)(bufBH + o) = vh;
            *(uint4*)(bufBL + o) = vl;
        }
        FENCE_ASYNC();
        __syncthreads();

        if (wid == 0) {
            if (elect_one_pred()) {
                uint64_t dAH = MK_DESC(sb + GM_BUF + s*65536);
                uint64_t dAL = dAH + (16384 >> 4);
                uint64_t dBH = dAH + (32768 >> 4);
                uint64_t dBL = dAH + (49152 >> 4);
#pragma unroll
                for (int m = 0; m < 3; ++m) {
                    uint64_t ad = (m == 2) ? dAL : dAH;
                    uint64_t bd = (m == 1) ? dBL : dBH;
#pragma unroll
                    for (int ks = 0; ks < 4; ++ks)
                        mma_f16_ss(tb, ad + ks*2, bd + ks*2, IDESC_128x128,
                                   !(ch == 0 && m == 0 && ks == 0));
                }
                TCG_COMMIT(sb + ((s == 0) ? GM_BAR0 : GM_BAR1));
            }
        }
    }
    MBAR_WAIT(sb + GM_BAR0, pv0);
    MBAR_WAIT(sb + GM_BAR1, pv1);
    TCG_FENCE_AFTER();

    // DIRECT epilogue: thread tid owns C row row0+tid (512B contiguous/thread)
    {
        float* crow = C + (size_t)(row0 + tid)*HID + col0;
#pragma unroll
        for (int hh = 0; hh < 4; ++hh) {
            uint32_t dr[32];
            TCG_LD_X32(dr, tb + hh*32);
            TCG_WAIT_LD();
#pragma unroll
            for (int g = 0; g < 8; ++g) {
                float4 bv = *(const float4*)(bias + col0 + hh*32 + 4*g);
                float4 o = make_float4(__uint_as_float(dr[4*g+0]) + bv.x,
                                       __uint_as_float(dr[4*g+1]) + bv.y,
                                       __uint_as_float(dr[4*g+2]) + bv.z,
                                       __uint_as_float(dr[4*g+3]) + bv.w);
                *(float4*)(crow + hh*32 + 4*g) = o;
            }
        }
    }

    __syncthreads();
    if (tid == 0) { MBAR_INVAL(sb + GM_BAR0); MBAR_INVAL(sb + GM_BAR1); }
    __syncthreads();
    if (wid == 0) TCG_DEALLOC(tb, 128);
#endif  // TCG_OK
}

// ===========================================================================
// cr_kernel (unchanged)
// ===========================================================================
__global__ void cr_kernel(const float* __restrict__ q, const float* __restrict__ k,
                          const float* __restrict__ rel, float* __restrict__ cr)
{
    int gw = (int)((blockIdx.x * blockDim.x + threadIdx.x) >> 5);
    int lane = threadIdx.x & 31;
    if (gw >= BSROWS*NH) return;
    int row = gw >> 3, h = gw & 7;
    const float* qp = q + (size_t)row*HID + h*DH;
    const float* kp = k + (size_t)row*HID + h*DH;
    float2 qv = *(const float2*)(qp + lane*2);
    float2 kv = *(const float2*)(kp + lane*2);
    float a0 = qv.x + kv.x, a1 = qv.y + kv.y;
#pragma unroll
    for (int r = 0; r < 3; ++r) {
        float2 rv = *(const float2*)(rel + r*DH + lane*2);
        float s = a0*rv.x + a1*rv.y;
        s += __shfl_xor_sync(0xffffffffu, s, 16);
        s += __shfl_xor_sync(0xffffffffu, s, 8);
        s += __shfl_xor_sync(0xffffffffu, s, 4);
        s += __shfl_xor_sync(0xffffffffu, s, 2);
        s += __shfl_xor_sync(0xffffffffu, s, 1);
        if (lane == 0) cr[(size_t)gw*4 + r] = s;
    }
    if (lane == 0) cr[(size_t)gw*4 + 3] = 0.f;
}

// ===========================================================================
// tcgen05 attention. Direct per-thread attn writes (staged writes removed —
// they added 4 syncs/iter for no gain), K/V + code prefetched into registers
// BEFORE the mbarrier waits to hide load latency behind MMA drains.
// ===========================================================================
#define SM_TPTR   0
#define SM_SBAR   8
#define SM_PVBAR  16
#define SM_QH     1024
#define SM_QL     17408
#define SM_KH     33792
#define SM_KL     41984
#define SM_VTH    50176
#define SM_VTL    58368
#define SM_TOTAL  66560

#define TM_S   0
#define TM_O   64
#define TM_PH  128
#define TM_PL  160
#define TM_COLS 256

__global__ __launch_bounds__(128) void attn_tc_kernel(
    const float* __restrict__ q, const float* __restrict__ k,
    const float* __restrict__ v, const float* __restrict__ cr,
    const unsigned char* __restrict__ code,
    float* __restrict__ attn, float* __restrict__ x, float* __restrict__ rinv)
{
#if TCG_OK
    extern __shared__ char smem8[];
    const uint32_t sb = smem_u32(smem8);
    const int tid = threadIdx.x;
    const int wid = tid >> 5;
    const int bh = blockIdx.y, b = bh >> 3, h = bh & 7;
    const int i0 = blockIdx.x * 128;
    const int gi = i0 + tid;
    const uint32_t woff = ((uint32_t)wid) << 21;

    if (wid == 0) TCG_ALLOC(sb + SM_TPTR, TM_COLS);
    if (tid == 0) { MBAR_INIT(sb + SM_SBAR, 1); MBAR_INIT(sb + SM_PVBAR, 1); }
    __syncthreads();
    uint32_t tb;
    asm volatile("ld.shared.b32 %0, [%1];" : "=r"(tb) : "r"(sb + SM_TPTR));

    {   // Q tile (128 x 64) -> split bf16, SW128, coalesced
#pragma unroll
        for (int pss = 0; pss < 16; ++pss) {
            int idx = pss*128 + tid;
            int row = idx >> 4, u = idx & 15;
            float4 a = *(const float4*)(q + (size_t)(b*SS + i0 + row)*HID + h*DH + 4*u);
            uint32_t h01 = pack_bf16x2(a.x, a.y);
            uint32_t h23 = pack_bf16x2(a.z, a.w);
            float r0 = a.x - __uint_as_float(h01 << 16);
            float r1 = a.y - __uint_as_float(h01 & 0xffff0000u);
            float r2 = a.z - __uint_as_float(h23 << 16);
            float r3 = a.w - __uint_as_float(h23 & 0xffff0000u);
            uint32_t o = SWZ((uint32_t)(row*128 + u*8));
            *(uint2*)(smem8 + SM_QH + o) = make_uint2(h01, h23);
            *(uint2*)(smem8 + SM_QL + o) = make_uint2(pack_bf16x2(r0, r1), pack_bf16x2(r2, r3));
        }
    }
    float c0, c1, c2;
    {
        const float* cp = cr + (size_t)((b*SS + gi)*NH + h)*4;
        c0 = cp[0]; c1 = cp[1]; c2 = cp[2];
    }
    FENCE_ASYNC();

    const uint64_t dQH = MK_DESC(sb + SM_QH), dQL = MK_DESC(sb + SM_QL);
    const uint64_t dKH = MK_DESC(sb + SM_KH), dKL = MK_DESC(sb + SM_KL);
    const uint64_t dVH = MK_DESC(sb + SM_VTH), dVL = MK_DESC(sb + SM_VTL);

    float rsum = 0.f;
    uint32_t sp = 0, pvp = 0;

    const int kvr = tid >> 1;              // this thread's K/V row (0..63)
    const int kvdc = (tid & 1) * 32;       // d half

    for (int t = 0, j0 = 0; j0 < SS; ++t, j0 += 64) {
        // -------- PREFETCH (before any wait): K/V rows + code bytes --------
        float4 kr[8], vr[8];
        {
            const float* krow = k + (size_t)(b*SS + j0 + kvr)*HID + h*DH + kvdc;
            const float* vrow = v + (size_t)(b*SS + j0 + kvr)*HID + h*DH + kvdc;
#pragma unroll
            for (int u = 0; u < 8; ++u) {
                kr[u] = *(const float4*)(krow + 4*u);
                vr[u] = *(const float4*)(vrow + 4*u);
            }
        }
        uint4 cwv[4];
        {
            const uint4* crow2 =
                (const uint4*)(code + (size_t)b*SS*SS + (size_t)gi*SS + j0);
            cwv[0] = crow2[0]; cwv[1] = crow2[1];
            cwv[2] = crow2[2]; cwv[3] = crow2[3];
        }

        if (t > 0) { MBAR_WAIT(sb + SM_PVBAR, pvp); pvp ^= 1; }
        __syncthreads();

        {   // K (64x64) split bf16 + V transposed, from prefetched regs
#pragma unroll
            for (int u = 0; u < 8; ++u) {
                int d0 = kvdc + 4*u;
                float4 a = kr[u];
                uint32_t h01 = pack_bf16x2(a.x, a.y);
                uint32_t h23 = pack_bf16x2(a.z, a.w);
                float r0 = a.x - __uint_as_float(h01 << 16);
                float r1 = a.y - __uint_as_float(h01 & 0xffff0000u);
                float r2 = a.z - __uint_as_float(h23 << 16);
                float r3 = a.w - __uint_as_float(h23 & 0xffff0000u);
                uint32_t o = SWZ((uint32_t)(kvr*128 + d0*2));
                *(uint2*)(smem8 + SM_KH + o) = make_uint2(h01, h23);
                *(uint2*)(smem8 + SM_KL + o) =
                    make_uint2(pack_bf16x2(r0, r1), pack_bf16x2(r2, r3));

                float4 vv = vr[u];
                float ve[4] = {vv.x, vv.y, vv.z, vv.w};
#pragma unroll
                for (int e = 0; e < 4; ++e) {
                    int d = d0 + e;
                    __nv_bfloat16 vh = __float2bfloat16(ve[e]);
                    __nv_bfloat16 vl = __float2bfloat16(ve[e] - __bfloat162float(vh));
                    uint32_t ov = SWZ((uint32_t)(d*128 + kvr*2));
                    *(__nv_bfloat16*)(smem8 + SM_VTH + ov) = vh;
                    *(__nv_bfloat16*)(smem8 + SM_VTL + ov) = vl;
                }
            }
        }
        FENCE_ASYNC();
        __syncthreads();

        // S = QhKh + QhKl + QlKh
        if (wid == 0) {
            if (elect_one_pred()) {
#pragma unroll
                for (int m = 0; m < 3; ++m) {
                    uint64_t ad = (m == 2) ? dQL : dQH;
                    uint64_t bd = (m == 1) ? dKL : dKH;
#pragma unroll
                    for (int ks = 0; ks < 4; ++ks)
                        mma_f16_ss(tb + TM_S, ad + ks*2, bd + ks*2, IDESC_128x64,
                                   !(m == 0 && ks == 0));
                }
                TCG_COMMIT(sb + SM_SBAR);
            }
        }
        MBAR_WAIT(sb + SM_SBAR, sp); sp ^= 1;
        TCG_FENCE_AFTER();

        // epilogue: two halves of 32 cols, direct per-thread attn writes
#pragma unroll
        for (int hh = 0; hh < 2; ++hh) {
            uint32_t sr[32];
            TCG_LD_X32(sr, tb + TM_S + hh*32);
            TCG_WAIT_LD();
            float p[32];
            const int jc0 = j0 + hh*32;
            uint32_t cw[8];
            cw[0]=cwv[2*hh].x; cw[1]=cwv[2*hh].y; cw[2]=cwv[2*hh].z; cw[3]=cwv[2*hh].w;
            cw[4]=cwv[2*hh+1].x; cw[5]=cwv[2*hh+1].y; cw[6]=cwv[2*hh+1].z; cw[7]=cwv[2*hh+1].w;
#pragma unroll
            for (int g = 0; g < 8; ++g) {
#pragma unroll
                for (int e = 0; e < 4; ++e) {
                    uint32_t cd = (cw[g] >> (8*e)) & 0xFFu;
                    float bias = (cd == 0) ? c0 : ((cd == 1) ? c1 :
                                 ((cd == 2) ? c2 : -3.0e10f));
                    float s = (__uint_as_float(sr[4*g + e]) + bias) * 0.125f;
                    float pe = __expf(s);      // masked -> exp(-3.75e9) = 0
                    p[4*g + e] = pe;
                    rsum += pe;
                }
            }
            {   // direct write: 8 consecutive float4 = one full 128B line
                float* arow = attn + ((size_t)bh*SS + gi)*SS + jc0;
#pragma unroll
                for (int g = 0; g < 8; ++g)
                    *(float4*)(arow + 4*g) =
                        make_float4(p[4*g], p[4*g+1], p[4*g+2], p[4*g+3]);
            }
            // pack P hi/lo -> TMEM
            uint32_t ph[16], pl[16];
#pragma unroll
            for (int c = 0; c < 16; ++c) {
                float p0 = p[2*c], p1 = p[2*c+1];
                uint32_t hp = pack_bf16x2(p0, p1);
                ph[c] = hp;
                pl[c] = pack_bf16x2(p0 - __uint_as_float(hp << 16),
                                    p1 - __uint_as_float(hp & 0xffff0000u));
            }
            TCG_ST_X16(tb + TM_PH + hh*16 + woff, ph);
            TCG_ST_X16(tb + TM_PL + hh*16 + woff, pl);
        }
        TCG_WAIT_ST();
        TCG_FENCE_BEFORE();
        __syncthreads();

        // O += PhVh + PhVl + PlVh
        if (wid == 0) {
            if (elect_one_pred()) {
                TCG_FENCE_AFTER();
#pragma unroll
                for (int m = 0; m < 3; ++m) {
                    uint32_t at = tb + ((m == 2) ? TM_PL : TM_PH);
                    uint64_t bd = (m == 1) ? dVL : dVH;
#pragma unroll
                    for (int ks = 0; ks < 4; ++ks)
                        mma_f16_ts(tb + TM_O, at + ks*8, bd + ks*2, IDESC_128x64,
                                   !(t == 0 && m == 0 && ks == 0));
                }
                TCG_COMMIT(sb + SM_PVBAR);
            }
        }
    }

    MBAR_WAIT(sb + SM_PVBAR, pvp);
    TCG_FENCE_AFTER();

    {
        float inv = 1.0f / rsum;
        rinv[(size_t)bh*SS + gi] = inv;
        float* xrow = x + (size_t)(b*SS + gi)*HID + h*DH;
#pragma unroll
        for (int hh = 0; hh < 2; ++hh) {
            uint32_t orw[32];
            TCG_LD_X32(orw, tb + TM_O + hh*32);
            TCG_WAIT_LD();
#pragma unroll
            for (int g = 0; g < 8; ++g) {
                float4 ov = make_float4(__uint_as_float(orw[4*g+0]) * inv,
                                        __uint_as_float(orw[4*g+1]) * inv,
                                        __uint_as_float(orw[4*g+2]) * inv,
                                        __uint_as_float(orw[4*g+3]) * inv);
                *(float4*)(xrow + hh*32 + 4*g) = ov;
            }
        }
    }

    __syncthreads();
    if (tid == 0) { MBAR_INVAL(sb + SM_SBAR); MBAR_INVAL(sb + SM_PVBAR); }
    __syncthreads();
    if (wid == 0) TCG_DEALLOC(tb, TM_COLS);
#endif  // TCG_OK
}

// ===========================================================================
// Normalize attn rows
// ===========================================================================
__global__ void norm_kernel(float* __restrict__ attn, const float* __restrict__ rinv)
{
    const size_t n4 = (size_t)BB*NH*SS*SS/4;
    for (size_t idx = (size_t)blockIdx.x*blockDim.x + threadIdx.x; idx < n4;
         idx += (size_t)gridDim.x*blockDim.x) {
        float inv = rinv[idx >> 9];
        float4 v = ((const float4*)attn)[idx];
        v.x *= inv; v.y *= inv; v.z *= inv; v.w *= inv;
        ((float4*)attn)[idx] = v;
    }
}

// ===========================================================================
extern "C" void kernel_launch(void* const* d_in, const int* in_sizes, int n_in,
                              void* d_out, int out_size)
{
    const float* query = (const float*)d_in[0];
    const float* key_  = (const float*)d_in[1];
    const float* value = (const float*)d_in[2];
    const unsigned char* mask = (const unsigned char*)d_in[3];
    const int*   pos   = (const int*)d_in[4];
    const float* Wq = (const float*)d_in[5];
    const float* bq = (const float*)d_in[6];
    const float* Wk = (const float*)d_in[7];
    const float* bk = (const float*)d_in[8];
    const float* Wv = (const float*)d_in[9];
    const float* bv = (const float*)d_in[10];
    const float* Wo = (const float*)d_in[11];
    const float* bo = (const float*)d_in[12];
    const float* rel = (const float*)d_in[13];

    float* out  = (float*)d_out;                     // (B,S,HID)
    float* attn = out + (size_t)BSROWS*HID;          // (B,H,S,S)

    float *qb, *kb, *vb, *xb, *crb, *rb;
    __nv_bfloat16 *wth, *wtl;
    unsigned char* codeb;
    cudaGetSymbolAddress((void**)&qb, g_q);
    cudaGetSymbolAddress((void**)&kb, g_k);
    cudaGetSymbolAddress((void**)&vb, g_v);
    cudaGetSymbolAddress((void**)&xb, g_x);
    cudaGetSymbolAddress((void**)&crb, g_cr);
    cudaGetSymbolAddress((void**)&rb, g_rinv);
    cudaGetSymbolAddress((void**)&wth, g_wth);
    cudaGetSymbolAddress((void**)&wtl, g_wtl);
    cudaGetSymbolAddress((void**)&codeb, g_code);

    cudaFuncSetAttribute(attn_tc_kernel,
                         cudaFuncAttributeMaxDynamicSharedMemorySize, SM_TOTAL);
    cudaFuncSetAttribute(gemm_tc_kernel,
                         cudaFuncAttributeMaxDynamicSharedMemorySize, GM_TOTAL);

    wprep_kernel<<<dim3(16, 16, 4), dim3(32, 8)>>>(Wq, Wk, Wv, Wo, wth, wtl);
    const size_t WSZ = (size_t)HID*HID;
    // QKV projections batched into ONE launch (grid.z selects A/W/bias/C)
    gemm_tc_kernel<<<dim3(HID/128, BSROWS/128, 3), 128, GM_TOTAL>>>(
        query, key_, value, wth, wtl, bq, bk, bv, qb, kb, vb);
    code_kernel<<<2048, 256>>>(pos, mask, codeb);

    cr_kernel<<<(BSROWS*NH*32 + 255)/256, 256>>>(qb, kb, rel, crb);

    attn_tc_kernel<<<dim3(SS/128, BB*NH), 128, SM_TOTAL>>>(
        qb, kb, vb, crb, codeb, attn, xb, rb);

    norm_kernel<<<2048, 256>>>(attn, rb);

    gemm_tc_kernel<<<dim3(HID/128, BSROWS/128, 1), 128, GM_TOTAL>>>(
        xb, nullptr, nullptr, wth + 3*WSZ, wtl + 3*WSZ, bo, nullptr, nullptr,
        out, nullptr, nullptr);
}

// round 13
// speedup vs baseline: 1.4302x; 1.0128x over previous
#include <cuda_runtime.h>
#include <cuda_bf16.h>
#include <cstdint>
#include <cstddef>

#define BB 2
#define SS 2048
#define HID 512
#define NH 8
#define DH 64
#define BSROWS (BB*SS)   // 4096

// tcgen05 is arch-SPECIFIC: only emit in sm_103a/sm_100a passes, never the
// generic compute_103 pass (ptxas rejects it there — Round-5 failure).
#if defined(__CUDA_ARCH_FEAT_SM103_ALL) || defined(__CUDA_ARCH_FEAT_SM100_ALL) || \
    (defined(__CUDA_ARCH_SPECIFIC__) && (__CUDA_ARCH_SPECIFIC__ >= 1000))
#define TCG_OK 1
#else
#define TCG_OK 0
#endif

// Scratch (device globals — allocation-free rule)
__device__ __align__(16) float g_q[BSROWS*HID];
__device__ __align__(16) float g_k[BSROWS*HID];
__device__ __align__(16) float g_v[BSROWS*HID];
__device__ __align__(16) float g_x[BSROWS*HID];
__device__ __align__(16) float g_cr[BSROWS*NH*4];
__device__ __align__(16) float g_rinv[BB*NH*SS];
__device__ __align__(16) __nv_bfloat16 g_wth[4*HID*HID];  // Wt[n,k] hi
__device__ __align__(16) __nv_bfloat16 g_wtl[4*HID*HID];  // Wt[n,k] lo
__device__ __align__(16) unsigned char g_code[(size_t)BB*SS*SS];  // mask?3:pos

// ===========================================================================
// PTX helpers (arch-specific passes only)
// ===========================================================================
#if TCG_OK
__device__ __forceinline__ uint32_t elect_one_pred() {
    uint32_t pred;
    asm volatile("{\n\t.reg .pred p;\n\telect.sync _|p, 0xFFFFFFFF;\n\t"
                 "selp.b32 %0, 1, 0, p;\n\t}" : "=r"(pred));
    return pred;
}
__device__ __forceinline__ uint32_t smem_u32(const void* p) {
    uint32_t a;
    asm("{ .reg .u64 t; cvta.to.shared.u64 t, %1; cvt.u32.u64 %0, t; }"
        : "=r"(a) : "l"(p));
    return a;
}
#define TCG_ALLOC(sa, n)   asm volatile("tcgen05.alloc.cta_group::1.sync.aligned.shared::cta.b32 [%0], %1;" :: "r"((uint32_t)(sa)), "r"((uint32_t)(n)) : "memory")
#define TCG_DEALLOC(t, n)  asm volatile("tcgen05.dealloc.cta_group::1.sync.aligned.b32 %0, %1;" :: "r"(t), "r"((uint32_t)(n)))
#define TCG_WAIT_LD()      asm volatile("tcgen05.wait::ld.sync.aligned;" ::: "memory")
#define TCG_WAIT_ST()      asm volatile("tcgen05.wait::st.sync.aligned;" ::: "memory")
#define TCG_FENCE_BEFORE() asm volatile("tcgen05.fence::before_thread_sync;" ::: "memory")
#define TCG_FENCE_AFTER()  asm volatile("tcgen05.fence::after_thread_sync;" ::: "memory")
#define TCG_COMMIT(mb)     asm volatile("tcgen05.commit.cta_group::1.mbarrier::arrive::one.shared::cluster.b64 [%0];" :: "r"((uint32_t)(mb)) : "memory")
#define FENCE_ASYNC()      asm volatile("fence.proxy.async.shared::cta;" ::: "memory")
#define MBAR_INIT(mb, c)   asm volatile("mbarrier.init.shared.b64 [%0], %1;" :: "r"((uint32_t)(mb)), "r"((uint32_t)(c)) : "memory")
#define MBAR_INVAL(mb)     asm volatile("mbarrier.inval.shared.b64 [%0];" :: "r"((uint32_t)(mb)) : "memory")

#define MBAR_WAIT(mb, ph) do { \
    uint32_t _m = (uint32_t)(mb), _p = (uint32_t)(ph), _d; \
    asm volatile("{\n\t.reg .pred p;\n\t" \
        "mbarrier.try_wait.parity.acquire.cta.shared::cta.b64 p, [%1], %2;\n\t" \
        "selp.b32 %0, 1, 0, p;\n\t}" : "=r"(_d) : "r"(_m), "r"(_p) : "memory"); \
    if (!_d) { \
        asm volatile("{\n\t.reg .pred P1;\n\t" \
            "WL_%=:\n\t" \
            "mbarrier.try_wait.parity.acquire.cta.shared::cta.b64 P1, [%0], %1, 0x989680;\n\t" \
            "@P1 bra.uni WD_%=;\n\t" \
            "bra.uni WL_%=;\n\t" \
            "WD_%=:\n\t}" :: "r"(_m), "r"(_p) : "memory"); \
    } \
} while (0)

#define TCG_LD_X32(r, ta) \
    asm volatile("tcgen05.ld.sync.aligned.32x32b.x32.b32 " \
        "{%0, %1, %2, %3, %4, %5, %6, %7, %8, %9, %10, %11, %12, %13, %14, %15, " \
        " %16, %17, %18, %19, %20, %21, %22, %23, %24, %25, %26, %27, %28, %29, %30, %31}, [%32];" \
        : "=r"((r)[0]),  "=r"((r)[1]),  "=r"((r)[2]),  "=r"((r)[3]), \
          "=r"((r)[4]),  "=r"((r)[5]),  "=r"((r)[6]),  "=r"((r)[7]), \
          "=r"((r)[8]),  "=r"((r)[9]),  "=r"((r)[10]), "=r"((r)[11]), \
          "=r"((r)[12]), "=r"((r)[13]), "=r"((r)[14]), "=r"((r)[15]), \
          "=r"((r)[16]), "=r"((r)[17]), "=r"((r)[18]), "=r"((r)[19]), \
          "=r"((r)[20]), "=r"((r)[21]), "=r"((r)[22]), "=r"((r)[23]), \
          "=r"((r)[24]), "=r"((r)[25]), "=r"((r)[26]), "=r"((r)[27]), \
          "=r"((r)[28]), "=r"((r)[29]), "=r"((r)[30]), "=r"((r)[31]) \
        : "r"(ta))

#define TCG_ST_X16(ta, r) \
    asm volatile("tcgen05.st.sync.aligned.32x32b.x16.b32 [%0], " \
        "{%1, %2, %3, %4, %5, %6, %7, %8, %9, %10, %11, %12, %13, %14, %15, %16};" \
        :: "r"(ta), \
           "r"((r)[0]),  "r"((r)[1]),  "r"((r)[2]),  "r"((r)[3]), \
           "r"((r)[4]),  "r"((r)[5]),  "r"((r)[6]),  "r"((r)[7]), \
           "r"((r)[8]),  "r"((r)[9]),  "r"((r)[10]), "r"((r)[11]), \
           "r"((r)[12]), "r"((r)[13]), "r"((r)[14]), "r"((r)[15]) \
        : "memory")

__device__ __forceinline__ void mma_f16_ss(uint32_t d_tmem, uint64_t a_desc,
                                           uint64_t b_desc, uint32_t idesc, bool acc) {
    uint32_t en = acc ? 1u : 0u;
    asm volatile("{\n\t.reg .pred p;\n\tsetp.ne.u32 p, %5, 0;\n\t"
        "tcgen05.mma.cta_group::1.kind::f16 [%0], %1, %2, %3, {%4, %4, %4, %4}, p;\n\t}"
        :: "r"(d_tmem), "l"(a_desc), "l"(b_desc), "r"(idesc), "r"(0u), "r"(en) : "memory");
}
__device__ __forceinline__ void mma_f16_ts(uint32_t d_tmem, uint32_t a_tmem,
                                           uint64_t b_desc, uint32_t idesc, bool acc) {
    uint32_t en = acc ? 1u : 0u;
    asm volatile("{\n\t.reg .pred p;\n\tsetp.ne.u32 p, %5, 0;\n\t"
        "tcgen05.mma.cta_group::1.kind::f16 [%0], [%1], %2, %3, {%4, %4, %4, %4}, p;\n\t}"
        :: "r"(d_tmem), "r"(a_tmem), "l"(b_desc), "r"(idesc), "r"(0u), "r"(en) : "memory");
}

static constexpr uint64_t SMEM_DESC_BASE_SW128 =
    (uint64_t(2) << 61) | (uint64_t(1) << 46) | (uint64_t(64) << 32) | (uint64_t(1) << 16);
#define MK_DESC(a) (SMEM_DESC_BASE_SW128 | ((uint64_t)((a) >> 4) & 0x3FFF))
#define SWZ(o) ((o) ^ (((o) >> 3) & 0x70))

__device__ __forceinline__ uint32_t pack_bf16x2(float lo, float hi) {
    uint32_t r; asm("cvt.rn.bf16x2.f32 %0, %1, %2;" : "=r"(r) : "f"(hi), "f"(lo));
    return r;
}

static constexpr uint32_t IDESC_128x64 =
    (1u << 4) | (1u << 7) | (1u << 10) | ((64u/8) << 17) | ((128u/16) << 24);
static constexpr uint32_t IDESC_128x128 =
    (1u << 4) | (1u << 7) | (1u << 10) | ((128u/8) << 17) | ((128u/16) << 24);
#endif  // TCG_OK

// ===========================================================================
// Weight prep: Wt[n,k] (hi/lo bf16) = transpose+split of W[k,n], all 4 mats.
// ===========================================================================
__global__ void wprep_kernel(const float* __restrict__ W0, const float* __restrict__ W1,
                             const float* __restrict__ W2, const float* __restrict__ W3,
                             __nv_bfloat16* __restrict__ wth, __nv_bfloat16* __restrict__ wtl)
{
    __shared__ float tile[32][33];
    const int z = blockIdx.z;
    const float* W = (z == 0) ? W0 : (z == 1) ? W1 : (z == 2) ? W2 : W3;
    const int n0 = blockIdx.x * 32, k0 = blockIdx.y * 32;
    const int tx = threadIdx.x, ty = threadIdx.y;
#pragma unroll
    for (int i = ty; i < 32; i += 8)
        tile[i][tx] = W[(size_t)(k0 + i)*HID + n0 + tx];
    __syncthreads();
#pragma unroll
    for (int i = ty; i < 32; i += 8) {
        float v = tile[tx][i];
        __nv_bfloat16 h = __float2bfloat16(v);
        __nv_bfloat16 l = __float2bfloat16(v - __bfloat162float(h));
        size_t o = (size_t)z*HID*HID + (size_t)(n0 + i)*HID + k0 + tx;
        wth[o] = h; wtl[o] = l;
    }
}

// ===========================================================================
// code prep: code[b,i,j] = mask[b,i,j] ? 3 : (uint8)pos[i,j]
// ===========================================================================
__global__ void code_kernel(const int* __restrict__ pos,
                            const unsigned char* __restrict__ mask,
                            unsigned char* __restrict__ code)
{
    const size_t n4 = (size_t)BB*SS*SS/4;
    const size_t ps4 = (size_t)SS*SS/4;
    for (size_t idx = (size_t)blockIdx.x*blockDim.x + threadIdx.x; idx < n4;
         idx += (size_t)gridDim.x*blockDim.x) {
        size_t prem = idx % ps4;
        int4 pp = *(const int4*)(pos + prem*4);
        uchar4 mm = ((const uchar4*)mask)[idx];
        uchar4 o;
        o.x = mm.x ? 3 : (unsigned char)pp.x;
        o.y = mm.y ? 3 : (unsigned char)pp.y;
        o.z = mm.z ? 3 : (unsigned char)pp.z;
        o.w = mm.w ? 3 : (unsigned char)pp.w;
        ((uchar4*)code)[idx] = o;
    }
}

// ===========================================================================
// tcgen05 GEMM, BATCHED over blockIdx.z (unchanged from R12 passing kernel)
// ===========================================================================
#define GM_TPTR   0
#define GM_BAR0   8
#define GM_BAR1   16
#define GM_BUF    1024
#define GM_TOTAL  (1024 + 2*65536)   // 132096

__global__ __launch_bounds__(128) void gemm_tc_kernel(
    const float* __restrict__ A0, const float* __restrict__ A1, const float* __restrict__ A2,
    const __nv_bfloat16* __restrict__ WthB, const __nv_bfloat16* __restrict__ WtlB,
    const float* __restrict__ b0, const float* __restrict__ b1, const float* __restrict__ b2,
    float* __restrict__ C0, float* __restrict__ C1, float* __restrict__ C2)
{
#if TCG_OK
    extern __shared__ char smem8[];
    const uint32_t sb = smem_u32(smem8);
    const int tid = threadIdx.x;
    const int wid = tid >> 5;
    const int z = blockIdx.z;
    const float* A    = (z == 0) ? A0 : (z == 1) ? A1 : A2;
    const float* bias = (z == 0) ? b0 : (z == 1) ? b1 : b2;
    float*       C    = (z == 0) ? C0 : (z == 1) ? C1 : C2;
    const __nv_bfloat16* Wth = WthB + (size_t)z*HID*HID;
    const __nv_bfloat16* Wtl = WtlB + (size_t)z*HID*HID;
    const int row0 = blockIdx.y * 128, col0 = blockIdx.x * 128;

    if (wid == 0) TCG_ALLOC(sb + GM_TPTR, 128);
    if (tid == 0) { MBAR_INIT(sb + GM_BAR0, 1); MBAR_INIT(sb + GM_BAR1, 1); }
    __syncthreads();
    uint32_t tb;
    asm volatile("ld.shared.b32 %0, [%1];" : "=r"(tb) : "r"(sb + GM_TPTR));

    uint32_t pv0 = 0, pv1 = 0;
    for (int ch = 0; ch < 8; ++ch) {
        const int s = ch & 1;
        char* bufAH = smem8 + GM_BUF + s*65536;
        char* bufAL = bufAH + 16384;
        char* bufBH = bufAH + 32768;
        char* bufBL = bufAH + 49152;
        float4 ar[4];
        uint4  br[2], blr[2];
#pragma unroll
        for (int pss = 0; pss < 4; ++pss) {
            ar[pss] = *(const float4*)(A + (size_t)(row0 + ((pss*128+tid) >> 4))*HID
                                        + ch*64 + 4*((pss*128+tid) & 15));
        }
#pragma unroll
        for (int pss = 0; pss < 2; ++pss) {
            int idx = pss*128 + tid;
            int n = idx >> 3, u = idx & 7;
            br[pss]  = *(const uint4*)(Wth + (size_t)(col0 + n)*HID + ch*64 + 8*u);
            blr[pss] = *(const uint4*)(Wtl + (size_t)(col0 + n)*HID + ch*64 + 8*u);
        }
        if (ch >= 2) {
            if (s == 0) { MBAR_WAIT(sb + GM_BAR0, pv0); pv0 ^= 1; }
            else        { MBAR_WAIT(sb + GM_BAR1, pv1); pv1 ^= 1; }
        }
        __syncthreads();

#pragma unroll
        for (int pss = 0; pss < 16; ++pss) {
            int idx = pss*128 + tid;
            int row = idx >> 4, u = idx & 15;
            float4 a = (pss < 4) ? ar[pss]
                     : *(const float4*)(A + (size_t)(row0 + row)*HID + ch*64 + 4*u);
            uint32_t h01 = pack_bf16x2(a.x, a.y);
            uint32_t h23 = pack_bf16x2(a.z, a.w);
            float r0 = a.x - __uint_as_float(h01 << 16);
            float r1 = a.y - __uint_as_float(h01 & 0xffff0000u);
            float r2 = a.z - __uint_as_float(h23 << 16);
            float r3 = a.w - __uint_as_float(h23 & 0xffff0000u);
            uint32_t o = SWZ((uint32_t)(row*128 + u*8));
            *(uint2*)(bufAH + o) = make_uint2(h01, h23);
            *(uint2*)(bufAL + o) = make_uint2(pack_bf16x2(r0, r1), pack_bf16x2(r2, r3));
        }
#pragma unroll
        for (int pss = 0; pss < 8; ++pss) {
            int idx = pss*128 + tid;
            int n = idx >> 3, u = idx & 7;
            uint32_t o = SWZ((uint32_t)(n*128 + u*16));
            uint4 vh = (pss < 2) ? br[pss]
                     : *(const uint4*)(Wth + (size_t)(col0 + n)*HID + ch*64 + 8*u);
            uint4 vl = (pss < 2) ? blr[pss]
                     : *(const uint4*)(Wtl + (size_t)(col0 + n)*HID + ch*64 + 8*u);
            *(uint4*)(bufBH + o) = vh;
            *(uint4*)(bufBL + o) = vl;
        }
        FENCE_ASYNC();
        __syncthreads();

        if (wid == 0) {
            if (elect_one_pred()) {
                uint64_t dAH = MK_DESC(sb + GM_BUF + s*65536);
                uint64_t dAL = dAH + (16384 >> 4);
                uint64_t dBH = dAH + (32768 >> 4);
                uint64_t dBL = dAH + (49152 >> 4);
#pragma unroll
                for (int m = 0; m < 3; ++m) {
                    uint64_t ad = (m == 2) ? dAL : dAH;
                    uint64_t bd = (m == 1) ? dBL : dBH;
#pragma unroll
                    for (int ks = 0; ks < 4; ++ks)
                        mma_f16_ss(tb, ad + ks*2, bd + ks*2, IDESC_128x128,
                                   !(ch == 0 && m == 0 && ks == 0));
                }
                TCG_COMMIT(sb + ((s == 0) ? GM_BAR0 : GM_BAR1));
            }
        }
    }
    MBAR_WAIT(sb + GM_BAR0, pv0);
    MBAR_WAIT(sb + GM_BAR1, pv1);
    TCG_FENCE_AFTER();

    {
        float* crow = C + (size_t)(row0 + tid)*HID + col0;
#pragma unroll
        for (int hh = 0; hh < 4; ++hh) {
            uint32_t dr[32];
            TCG_LD_X32(dr, tb + hh*32);
            TCG_WAIT_LD();
#pragma unroll
            for (int g = 0; g < 8; ++g) {
                float4 bv = *(const float4*)(bias + col0 + hh*32 + 4*g);
                float4 o = make_float4(__uint_as_float(dr[4*g+0]) + bv.x,
                                       __uint_as_float(dr[4*g+1]) + bv.y,
                                       __uint_as_float(dr[4*g+2]) + bv.z,
                                       __uint_as_float(dr[4*g+3]) + bv.w);
                *(float4*)(crow + hh*32 + 4*g) = o;
            }
        }
    }

    __syncthreads();
    if (tid == 0) { MBAR_INVAL(sb + GM_BAR0); MBAR_INVAL(sb + GM_BAR1); }
    __syncthreads();
    if (wid == 0) TCG_DEALLOC(tb, 128);
#endif  // TCG_OK
}

// ===========================================================================
// cr_kernel (unchanged)
// ===========================================================================
__global__ void cr_kernel(const float* __restrict__ q, const float* __restrict__ k,
                          const float* __restrict__ rel, float* __restrict__ cr)
{
    int gw = (int)((blockIdx.x * blockDim.x + threadIdx.x) >> 5);
    int lane = threadIdx.x & 31;
    if (gw >= BSROWS*NH) return;
    int row = gw >> 3, h = gw & 7;
    const float* qp = q + (size_t)row*HID + h*DH;
    const float* kp = k + (size_t)row*HID + h*DH;
    float2 qv = *(const float2*)(qp + lane*2);
    float2 kv = *(const float2*)(kp + lane*2);
    float a0 = qv.x + kv.x, a1 = qv.y + kv.y;
#pragma unroll
    for (int r = 0; r < 3; ++r) {
        float2 rv = *(const float2*)(rel + r*DH + lane*2);
        float s = a0*rv.x + a1*rv.y;
        s += __shfl_xor_sync(0xffffffffu, s, 16);
        s += __shfl_xor_sync(0xffffffffu, s, 8);
        s += __shfl_xor_sync(0xffffffffu, s, 4);
        s += __shfl_xor_sync(0xffffffffu, s, 2);
        s += __shfl_xor_sync(0xffffffffu, s, 1);
        if (lane == 0) cr[(size_t)gw*4 + r] = s;
    }
    if (lane == 0) cr[(size_t)gw*4 + 3] = 0.f;
}

// ===========================================================================
// tcgen05 attention, SOFTWARE-PIPELINED:
//   S double-buffered in TMEM (S0/S1), K/V smem double-buffered.
//   At iter t: prefetch KV(t+1), wait PV(t-1), convert KV(t+1) into alt
//   stage, issue S(t+1) -> then consume S(t) (already done: issued 1 iter
//   ago). S-MMA latency completely hidden. TMEM alloc stays 256 cols so
//   2-CTA/SM occupancy is preserved.
// Barrier ledger: sbar0/sbar1 alternate commit->wait (lead<=1 phase each);
// pvbar commit(t)/wait(t+1) (lead 1). Parity-safe per Round-9 rule.
// ===========================================================================
#define SM_TPTR   0
#define SM_SBAR0  8
#define SM_SBAR1  16
#define SM_PVBAR  24
#define SM_QH     1024                    // 16KB
#define SM_QL     17408                   // 16KB
// KV stage s (s=0,1): base 33792 + s*32768; KH|KL|VTH|VTL, 8KB each
#define SM_KV     33792
#define SM_TOTAL  (33792 + 2*32768)       // 99328

#define TM_S0  0
#define TM_S1  64
#define TM_O   128
#define TM_PH  192
#define TM_PL  224
#define TM_COLS 256

__global__ __launch_bounds__(128) void attn_tc_kernel(
    const float* __restrict__ q, const float* __restrict__ k,
    const float* __restrict__ v, const float* __restrict__ cr,
    const unsigned char* __restrict__ code,
    float* __restrict__ attn, float* __restrict__ x, float* __restrict__ rinv)
{
#if TCG_OK
    extern __shared__ char smem8[];
    const uint32_t sb = smem_u32(smem8);
    const int tid = threadIdx.x;
    const int wid = tid >> 5;
    const int bh = blockIdx.y, b = bh >> 3, h = bh & 7;
    const int i0 = blockIdx.x * 128;
    const int gi = i0 + tid;
    const uint32_t woff = ((uint32_t)wid) << 21;

    if (wid == 0) TCG_ALLOC(sb + SM_TPTR, TM_COLS);
    if (tid == 0) {
        MBAR_INIT(sb + SM_SBAR0, 1); MBAR_INIT(sb + SM_SBAR1, 1);
        MBAR_INIT(sb + SM_PVBAR, 1);
    }
    __syncthreads();
    uint32_t tb;
    asm volatile("ld.shared.b32 %0, [%1];" : "=r"(tb) : "r"(sb + SM_TPTR));

    {   // Q tile (128 x 64) -> split bf16, SW128, coalesced
#pragma unroll
        for (int pss = 0; pss < 16; ++pss) {
            int idx = pss*128 + tid;
            int row = idx >> 4, u = idx & 15;
            float4 a = *(const float4*)(q + (size_t)(b*SS + i0 + row)*HID + h*DH + 4*u);
            uint32_t h01 = pack_bf16x2(a.x, a.y);
            uint32_t h23 = pack_bf16x2(a.z, a.w);
            float r0 = a.x - __uint_as_float(h01 << 16);
            float r1 = a.y - __uint_as_float(h01 & 0xffff0000u);
            float r2 = a.z - __uint_as_float(h23 << 16);
            float r3 = a.w - __uint_as_float(h23 & 0xffff0000u);
            uint32_t o = SWZ((uint32_t)(row*128 + u*8));
            *(uint2*)(smem8 + SM_QH + o) = make_uint2(h01, h23);
            *(uint2*)(smem8 + SM_QL + o) = make_uint2(pack_bf16x2(r0, r1), pack_bf16x2(r2, r3));
        }
    }
    float c0, c1, c2;
    {
        const float* cp = cr + (size_t)((b*SS + gi)*NH + h)*4;
        c0 = cp[0]; c1 = cp[1]; c2 = cp[2];
    }

    const uint64_t dQH = MK_DESC(sb + SM_QH), dQL = MK_DESC(sb + SM_QL);

    float rsum = 0.f;
    uint32_t sp0 = 0, sp1 = 0, pvp = 0;

    const int kvr = tid >> 1;              // this thread's K/V row (0..63)
    const int kvdc = (tid & 1) * 32;       // d half

    // ---- convert K/V tile j into smem stage s (from prefetched regs) ----
    auto convert_kv = [&](int s, const float4* kr, const float4* vr) {
        char* base = smem8 + SM_KV + s*32768;
        char* cKH = base;          char* cKL = base + 8192;
        char* cVTH = base + 16384; char* cVTL = base + 24576;
#pragma unroll
        for (int u = 0; u < 8; ++u) {
            int d0 = kvdc + 4*u;
            float4 a = kr[u];
            uint32_t h01 = pack_bf16x2(a.x, a.y);
            uint32_t h23 = pack_bf16x2(a.z, a.w);
            float r0 = a.x - __uint_as_float(h01 << 16);
            float r1 = a.y - __uint_as_float(h01 & 0xffff0000u);
            float r2 = a.z - __uint_as_float(h23 << 16);
            float r3 = a.w - __uint_as_float(h23 & 0xffff0000u);
            uint32_t o = SWZ((uint32_t)(kvr*128 + d0*2));
            *(uint2*)(cKH + o) = make_uint2(h01, h23);
            *(uint2*)(cKL + o) = make_uint2(pack_bf16x2(r0, r1), pack_bf16x2(r2, r3));
            float4 vv = vr[u];
            float ve[4] = {vv.x, vv.y, vv.z, vv.w};
#pragma unroll
            for (int e = 0; e < 4; ++e) {
                int d = d0 + e;
                __nv_bfloat16 vh = __float2bfloat16(ve[e]);
                __nv_bfloat16 vl = __float2bfloat16(ve[e] - __bfloat162float(vh));
                uint32_t ov = SWZ((uint32_t)(d*128 + kvr*2));
                *(__nv_bfloat16*)(cVTH + ov) = vh;
                *(__nv_bfloat16*)(cVTL + ov) = vl;
            }
        }
    };
    auto issue_S = [&](int s, bool first_dummy) {
        (void)first_dummy;
        if (wid == 0) {
            if (elect_one_pred()) {
                uint32_t kbase = sb + SM_KV + s*32768;
                uint64_t dKH = MK_DESC(kbase), dKL = MK_DESC(kbase + 8192);
                uint32_t sdst = tb + ((s == 0) ? TM_S0 : TM_S1);
#pragma unroll
                for (int m = 0; m < 3; ++m) {
                    uint64_t ad = (m == 2) ? dQL : dQH;
                    uint64_t bd = (m == 1) ? dKL : dKH;
#pragma unroll
                    for (int ks = 0; ks < 4; ++ks)
                        mma_f16_ss(sdst, ad + ks*2, bd + ks*2, IDESC_128x64,
                                   !(m == 0 && ks == 0));
                }
                TCG_COMMIT(sb + ((s == 0) ? SM_SBAR0 : SM_SBAR1));
            }
        }
    };

    // ---- preamble: KV(0) -> stage 0, issue S(0) ----
    {
        float4 kr[8], vr[8];
        const float* krow = k + (size_t)(b*SS + kvr)*HID + h*DH + kvdc;
        const float* vrow = v + (size_t)(b*SS + kvr)*HID + h*DH + kvdc;
#pragma unroll
        for (int u = 0; u < 8; ++u) {
            kr[u] = *(const float4*)(krow + 4*u);
            vr[u] = *(const float4*)(vrow + 4*u);
        }
        convert_kv(0, kr, vr);
        FENCE_ASYNC();
        __syncthreads();   // Q + KV(0) visible
        issue_S(0, true);
    }

    for (int t = 0, j0 = 0; j0 < SS; ++t, j0 += 64) {
        const int s = t & 1;
        // ---- prefetch KV(t+1) + code(t) before any wait ----
        float4 kr[8], vr[8];
        if (t < 31) {
            const float* krow = k + (size_t)(b*SS + j0 + 64 + kvr)*HID + h*DH + kvdc;
            const float* vrow = v + (size_t)(b*SS + j0 + 64 + kvr)*HID + h*DH + kvdc;
#pragma unroll
            for (int u = 0; u < 8; ++u) {
                kr[u] = *(const float4*)(krow + 4*u);
                vr[u] = *(const float4*)(vrow + 4*u);
            }
        }
        uint4 cwv[4];
        {
            const uint4* crow2 =
                (const uint4*)(code + (size_t)b*SS*SS + (size_t)gi*SS + j0);
            cwv[0] = crow2[0]; cwv[1] = crow2[1];
            cwv[2] = crow2[2]; cwv[3] = crow2[3];
        }

        // ---- wait PV(t-1): frees P TMEM and KV stage (t+1)&1 ----
        if (t >= 1) { MBAR_WAIT(sb + SM_PVBAR, pvp); pvp ^= 1; }
        __syncthreads();

        // ---- convert KV(t+1) into alt stage, issue S(t+1) ----
        if (t < 31) {
            convert_kv(1 - s, kr, vr);
            FENCE_ASYNC();
            __syncthreads();
            issue_S(1 - s, false);
        }

        // ---- wait S(t) (issued one iteration ago -> usually ready) ----
        if (s == 0) { MBAR_WAIT(sb + SM_SBAR0, sp0); sp0 ^= 1; }
        else        { MBAR_WAIT(sb + SM_SBAR1, sp1); sp1 ^= 1; }
        TCG_FENCE_AFTER();

        // ---- epilogue on S(t) ----
        const uint32_t sbase = tb + ((s == 0) ? TM_S0 : TM_S1);
#pragma unroll
        for (int hh = 0; hh < 2; ++hh) {
            uint32_t sr[32];
            TCG_LD_X32(sr, sbase + hh*32);
            TCG_WAIT_LD();
            float p[32];
            const int jc0 = j0 + hh*32;
            uint32_t cw[8];
            cw[0]=cwv[2*hh].x; cw[1]=cwv[2*hh].y; cw[2]=cwv[2*hh].z; cw[3]=cwv[2*hh].w;
            cw[4]=cwv[2*hh+1].x; cw[5]=cwv[2*hh+1].y; cw[6]=cwv[2*hh+1].z; cw[7]=cwv[2*hh+1].w;
#pragma unroll
            for (int g = 0; g < 8; ++g) {
#pragma unroll
                for (int e = 0; e < 4; ++e) {
                    uint32_t cd = (cw[g] >> (8*e)) & 0xFFu;
                    float bias = (cd == 0) ? c0 : ((cd == 1) ? c1 :
                                 ((cd == 2) ? c2 : -3.0e10f));
                    float sc = (__uint_as_float(sr[4*g + e]) + bias) * 0.125f;
                    float pe = __expf(sc);     // masked -> exp(-3.75e9) = 0
                    p[4*g + e] = pe;
                    rsum += pe;
                }
            }
            {   // direct write: one full 128B line per thread
                float* arow = attn + ((size_t)bh*SS + gi)*SS + jc0;
#pragma unroll
                for (int g = 0; g < 8; ++g)
                    *(float4*)(arow + 4*g) =
                        make_float4(p[4*g], p[4*g+1], p[4*g+2], p[4*g+3]);
            }
            uint32_t ph[16], pl[16];
#pragma unroll
            for (int c = 0; c < 16; ++c) {
                float p0 = p[2*c], p1 = p[2*c+1];
                uint32_t hp = pack_bf16x2(p0, p1);
                ph[c] = hp;
                pl[c] = pack_bf16x2(p0 - __uint_as_float(hp << 16),
                                    p1 - __uint_as_float(hp & 0xffff0000u));
            }
            TCG_ST_X16(tb + TM_PH + hh*16 + woff, ph);
            TCG_ST_X16(tb + TM_PL + hh*16 + woff, pl);
        }
        TCG_WAIT_ST();
        TCG_FENCE_BEFORE();
        __syncthreads();

        // ---- PV(t): O += PhVh + PhVl + PlVh (V from stage s) ----
        if (wid == 0) {
            if (elect_one_pred()) {
                TCG_FENCE_AFTER();
                uint32_t vbase = sb + SM_KV + s*32768 + 16384;
                uint64_t dVH = MK_DESC(vbase), dVL = MK_DESC(vbase + 8192);
#pragma unroll
                for (int m = 0; m < 3; ++m) {
                    uint32_t at = tb + ((m == 2) ? TM_PL : TM_PH);
                    uint64_t bd = (m == 1) ? dVL : dVH;
#pragma unroll
                    for (int ks = 0; ks < 4; ++ks)
                        mma_f16_ts(tb + TM_O, at + ks*8, bd + ks*2, IDESC_128x64,
                                   !(t == 0 && m == 0 && ks == 0));
                }
                TCG_COMMIT(sb + SM_PVBAR);
            }
        }
    }

    MBAR_WAIT(sb + SM_PVBAR, pvp);   // PV(31)
    TCG_FENCE_AFTER();

    {
        float inv = 1.0f / rsum;
        rinv[(size_t)bh*SS + gi] = inv;
        float* xrow = x + (size_t)(b*SS + gi)*HID + h*DH;
#pragma unroll
        for (int hh = 0; hh < 2; ++hh) {
            uint32_t orw[32];
            TCG_LD_X32(orw, tb + TM_O + hh*32);
            TCG_WAIT_LD();
#pragma unroll
            for (int g = 0; g < 8; ++g) {
                float4 ov = make_float4(__uint_as_float(orw[4*g+0]) * inv,
                                        __uint_as_float(orw[4*g+1]) * inv,
                                        __uint_as_float(orw[4*g+2]) * inv,
                                        __uint_as_float(orw[4*g+3]) * inv);
                *(float4*)(xrow + hh*32 + 4*g) = ov;
            }
        }
    }

    __syncthreads();
    if (tid == 0) {
        MBAR_INVAL(sb + SM_SBAR0); MBAR_INVAL(sb + SM_SBAR1);
        MBAR_INVAL(sb + SM_PVBAR);
    }
    __syncthreads();
    if (wid == 0) TCG_DEALLOC(tb, TM_COLS);
#endif  // TCG_OK
}

// ===========================================================================
// Normalize attn rows
// ===========================================================================
__global__ void norm_kernel(float* __restrict__ attn, const float* __restrict__ rinv)
{
    const size_t n4 = (size_t)BB*NH*SS*SS/4;
    for (size_t idx = (size_t)blockIdx.x*blockDim.x + threadIdx.x; idx < n4;
         idx += (size_t)gridDim.x*blockDim.x) {
        float inv = rinv[idx >> 9];
        float4 v = ((const float4*)attn)[idx];
        v.x *= inv; v.y *= inv; v.z *= inv; v.w *= inv;
        ((float4*)attn)[idx] = v;
    }
}

// ===========================================================================
extern "C" void kernel_launch(void* const* d_in, const int* in_sizes, int n_in,
                              void* d_out, int out_size)
{
    const float* query = (const float*)d_in[0];
    const float* key_  = (const float*)d_in[1];
    const float* value = (const float*)d_in[2];
    const unsigned char* mask = (const unsigned char*)d_in[3];
    const int*   pos   = (const int*)d_in[4];
    const float* Wq = (const float*)d_in[5];
    const float* bq = (const float*)d_in[6];
    const float* Wk = (const float*)d_in[7];
    const float* bk = (const float*)d_in[8];
    const float* Wv = (const float*)d_in[9];
    const float* bv = (const float*)d_in[10];
    const float* Wo = (const float*)d_in[11];
    const float* bo = (const float*)d_in[12];
    const float* rel = (const float*)d_in[13];

    float* out  = (float*)d_out;                     // (B,S,HID)
    float* attn = out + (size_t)BSROWS*HID;          // (B,H,S,S)

    float *qb, *kb, *vb, *xb, *crb, *rb;
    __nv_bfloat16 *wth, *wtl;
    unsigned char* codeb;
    cudaGetSymbolAddress((void**)&qb, g_q);
    cudaGetSymbolAddress((void**)&kb, g_k);
    cudaGetSymbolAddress((void**)&vb, g_v);
    cudaGetSymbolAddress((void**)&xb, g_x);
    cudaGetSymbolAddress((void**)&crb, g_cr);
    cudaGetSymbolAddress((void**)&rb, g_rinv);
    cudaGetSymbolAddress((void**)&wth, g_wth);
    cudaGetSymbolAddress((void**)&wtl, g_wtl);
    cudaGetSymbolAddress((void**)&codeb, g_code);

    cudaFuncSetAttribute(attn_tc_kernel,
                         cudaFuncAttributeMaxDynamicSharedMemorySize, SM_TOTAL);
    cudaFuncSetAttribute(gemm_tc_kernel,
                         cudaFuncAttributeMaxDynamicSharedMemorySize, GM_TOTAL);

    wprep_kernel<<<dim3(16, 16, 4), dim3(32, 8)>>>(Wq, Wk, Wv, Wo, wth, wtl);
    const size_t WSZ = (size_t)HID*HID;
    gemm_tc_kernel<<<dim3(HID/128, BSROWS/128, 3), 128, GM_TOTAL>>>(
        query, key_, value, wth, wtl, bq, bk, bv, qb, kb, vb);
    code_kernel<<<2048, 256>>>(pos, mask, codeb);

    cr_kernel<<<(BSROWS*NH*32 + 255)/256, 256>>>(qb, kb, rel, crb);

    attn_tc_kernel<<<dim3(SS/128, BB*NH), 128, SM_TOTAL>>>(
        qb, kb, vb, crb, codeb, attn, xb, rb);

    norm_kernel<<<2048, 256>>>(attn, rb);

    gemm_tc_kernel<<<dim3(HID/128, BSROWS/128, 1), 128, GM_TOTAL>>>(
        xb, nullptr, nullptr, wth + 3*WSZ, wtl + 3*WSZ, bo, nullptr, nullptr,
        out, nullptr, nullptr);
}